// round 10
// baseline (speedup 1.0000x reference)
#include <cuda_runtime.h>
#include <cuda_fp16.h>
#include <cstdint>
#include <math.h>

// Problem constants
#define BATCH   2
#define SEQ     2048
#define HID     1024
#define NHEADS  16
#define HD      64
#define QKV_N   3072
#define MROWS   4096
#define KS      2048          // stacked K = 2*1024 (2-pass: B split, A single limb)

#define QSCALE  0.18033688f   // 0.125 * log2(e)

// ---------------- scratch (device globals; no allocations allowed) ----------
__device__ __half g_as[(size_t)MROWS * KS];            // stacked activations [a|a]
__device__ __half g_wqkv_s[(size_t)QKV_N * KS];        // stacked W^T [bh|bl]
__device__ __half g_wout_s[(size_t)HID * KS];
// Head-major fp16 Q (single limb) and hi/lo K/V: [b*16+h][s][64]
#define HM_ELEMS ((size_t)BATCH * NHEADS * SEQ * HD)
__device__ __half g_qh[HM_ELEMS];
__device__ __half g_kh[HM_ELEMS], g_kl[HM_ELEMS];
__device__ __half g_vh[HM_ELEMS], g_vl[HM_ELEMS];

// ---------------- PTX helpers (base ISA only) ----------------
__device__ __forceinline__ uint32_t smem_u32(const void* p) {
    uint32_t a;
    asm("{ .reg .u64 t; cvta.to.shared.u64 t, %1; cvt.u32.u64 %0, t; }" : "=r"(a) : "l"(p));
    return a;
}

__device__ __forceinline__ void cp_async16(uint32_t s, const void* g) {
    asm volatile("cp.async.cg.shared.global [%0], [%1], 16;" :: "r"(s), "l"(g) : "memory");
}
#define CP_COMMIT() asm volatile("cp.async.commit_group;" ::: "memory")
#define CP_WAIT1()  asm volatile("cp.async.wait_group 1;"  ::: "memory")

#define LDSM_X4(R0, R1, R2, R3, ADDR)                                          \
    asm volatile("ldmatrix.sync.aligned.m8n8.x4.shared.b16 {%0,%1,%2,%3}, [%4];" \
                 : "=r"(R0), "=r"(R1), "=r"(R2), "=r"(R3) : "r"(ADDR))

#define LDSM_X4T(R0, R1, R2, R3, ADDR)                                         \
    asm volatile("ldmatrix.sync.aligned.m8n8.x4.trans.shared.b16 {%0,%1,%2,%3}, [%4];" \
                 : "=r"(R0), "=r"(R1), "=r"(R2), "=r"(R3) : "r"(ADDR))

// fp16 inputs, f32 accumulate (main pass)
#define MMAF32(D, A, B0, B1)                                                   \
    asm volatile("mma.sync.aligned.m16n8k16.row.col.f32.f16.f16.f32 "          \
                 "{%0,%1,%2,%3},{%4,%5,%6,%7},{%8,%9},{%0,%1,%2,%3};"          \
                 : "+f"((D)[0]), "+f"((D)[1]), "+f"((D)[2]), "+f"((D)[3])      \
                 : "r"((A)[0]), "r"((A)[1]), "r"((A)[2]), "r"((A)[3]),         \
                   "r"(B0), "r"(B1))

// fp16 inputs, f16 accumulate (cross pass; values ~2^-11 of main)
#define MMAF16(D, A, B0, B1)                                                   \
    asm volatile("mma.sync.aligned.m16n8k16.row.col.f16.f16.f16.f16 "          \
                 "{%0,%1},{%2,%3,%4,%5},{%6,%7},{%0,%1};"                      \
                 : "+r"((D)[0]), "+r"((D)[1])                                  \
                 : "r"((A)[0]), "r"((A)[1]), "r"((A)[2]), "r"((A)[3]),         \
                   "r"(B0), "r"(B1))

// Fast exp2 on FMA/ALU pipes (no MUFU). rel err ~1e-7.
__device__ __forceinline__ float fexp2(float x) {
    x = fmaxf(x, -125.0f);
    int   n  = __float2int_rn(x);
    float f  = x - (float)n;
    float p  = 1.535336188319500e-4f;
    p = fmaf(p, f, 1.339887440266574e-3f);
    p = fmaf(p, f, 9.618437357674640e-3f);
    p = fmaf(p, f, 5.550332471162809e-2f);
    p = fmaf(p, f, 2.402264791363012e-1f);
    p = fmaf(p, f, 6.931472028550421e-1f);
    p = fmaf(p, f, 1.0f);
    return __int_as_float(__float_as_int(p) + (n << 23));
}

__device__ __forceinline__ uint32_t pack2h(__half a, __half b) {
    __half2 t;
    t.x = a; t.y = b;
    return *reinterpret_cast<uint32_t*>(&t);
}

// ---------------------------------------------------------------------------
// Conversion: fp32 activations [R,1024] -> stacked fp16 [R,2048] = [a | a]
// Vectorized: one float4 (4 elems) per thread-iteration, uint2 stores.
// ---------------------------------------------------------------------------
__global__ __launch_bounds__(256) void convert_act_kernel(
    const float* __restrict__ in, __half* __restrict__ out, int R)
{
    int idx = blockIdx.x * 256 + threadIdx.x;     // over R*256 float4s
    if (idx >= R * 256) return;
    const int m  = idx >> 8;
    const int k4 = (idx & 255) * 4;
    const float4 v = ((const float4*)in)[idx];
    uint2 h;
    h.x = pack2h(__float2half(v.x), __float2half(v.y));
    h.y = pack2h(__float2half(v.z), __float2half(v.w));
    const size_t o = (size_t)m * KS + k4;
    *(uint2*)(out + o)        = h;
    *(uint2*)(out + o + 1024) = h;
}

// ---------------------------------------------------------------------------
// Conversion + transpose: W fp32 [K=1024, N] -> stacked fp16 [N,2048]=[bh|bl]
// ---------------------------------------------------------------------------
__global__ __launch_bounds__(1024) void convert_w_kernel(
    const float* __restrict__ w, __half* __restrict__ out, int N)
{
    __shared__ float tile[32][33];
    int tx = threadIdx.x & 31;
    int ty = threadIdx.x >> 5;
    int gn = blockIdx.x * 32;
    int gk = blockIdx.y * 32;
    tile[ty][tx] = w[(size_t)(gk + ty) * N + gn + tx];
    __syncthreads();
    float v = tile[tx][ty];
    __half h = __float2half(v);
    __half l = __float2half(v - __half2float(h));
    size_t o = (size_t)(gn + ty) * KS + gk + tx;
    out[o]        = h;
    out[o + 1024] = l;
}

// ---------------------------------------------------------------------------
// HMMA GEMM: C[4096,N] = As[4096,2048] @ Bs[N,2048]^T + bias.
// CTA tile 128x64, 256 threads (8 warps, 4x2), warp tile 32x32.
// Phase 1 (iters 0-15,  a*bh): f32 accumulate.
// Phase 2 (iters 16-31, a*bl): f16 accumulate, folded at end.
// mode 0: fp32 C out.  mode 1: QKV epilogue -> fp16 Q (single) / K,V hi-lo.
// ---------------------------------------------------------------------------
#define BM 128
#define BN 64
#define BK 64
#define NKITER (KS / BK)                   // 32
#define NPH1   16                          // iters of the f32-acc main phase
#define A_BYTES (BM * 128)                 // 16 KB
#define B_BYTES (BN * 128)                 // 8 KB
#define STAGE_BYTES (A_BYTES + B_BYTES)    // 24 KB
#define GEMM_SMEM (3 * STAGE_BYTES + 128)

__global__ __launch_bounds__(256, 2) void mma_gemm_kernel(
    const __half* __restrict__ As, const __half* __restrict__ Bs,
    const float* __restrict__ bias, float* __restrict__ C, int N, int mode,
    __half* __restrict__ qh,
    __half* __restrict__ kh, __half* __restrict__ kl,
    __half* __restrict__ vh, __half* __restrict__ vl)
{
    extern __shared__ char dsmem[];
    const uint32_t smem_base = (smem_u32(dsmem) + 127u) & ~127u;

    const int tid  = threadIdx.x;
    const int wid  = tid >> 5;
    const int lane = tid & 31;
    const int wm   = wid >> 1;     // 0..3 (32-row slab)
    const int wn   = wid & 1;      // 0..1 (32-col slab)

    const int block_row = blockIdx.y * BM;
    const int block_col = blockIdx.x * BN;

    const __half* Abase = As + (size_t)block_row * KS;
    const __half* Bbase = Bs + (size_t)block_col * KS;

    auto load_stage = [&](int stage, int kc) {
        const uint32_t sA = smem_base + stage * STAGE_BYTES;
        const uint32_t sB = sA + A_BYTES;
#pragma unroll
        for (int i = 0; i < 4; i++) {       // A: 1024 16B segs
            const int s   = i * 256 + tid;
            const int row = s >> 3;
            const int ch  = s & 7;
            const uint32_t sw = (uint32_t)(ch * 16) ^ (uint32_t)((row & 7) << 4);
            cp_async16(sA + row * 128 + sw, Abase + (size_t)row * KS + kc + ch * 8);
        }
#pragma unroll
        for (int i = 0; i < 2; i++) {       // B: 512 16B segs
            const int s   = i * 256 + tid;
            const int row = s >> 3;
            const int ch  = s & 7;
            const uint32_t sw = (uint32_t)(ch * 16) ^ (uint32_t)((row & 7) << 4);
            cp_async16(sB + row * 128 + sw, Bbase + (size_t)row * KS + kc + ch * 8);
        }
        CP_COMMIT();
    };

    float    facc[2][4][4];
    uint32_t hacc[2][4][2];
#pragma unroll
    for (int mt = 0; mt < 2; mt++)
#pragma unroll
        for (int nt = 0; nt < 4; nt++) {
#pragma unroll
            for (int r = 0; r < 4; r++) facc[mt][nt][r] = 0.0f;
            hacc[mt][nt][0] = 0u; hacc[mt][nt][1] = 0u;
        }

    load_stage(0, 0);
    load_stage(1, BK);

    const int lrow  = lane & 15;
    const int kseg  = (lane >> 4) * 16;
    const uint32_t arow_off = (uint32_t)(wm * 32 + lrow) * 128;
    const uint32_t brow_off = (uint32_t)(wn * 32 + lrow) * 128;
    const uint32_t aswz = (uint32_t)((lrow & 7) << 4);

    // ---- phase 1: main term a*bh, f32 accumulate ----
    for (int it = 0; it < NPH1; it++) {
        CP_WAIT1();
        __syncthreads();
        load_stage((it + 2) % 3, (it + 2) * BK);
        const uint32_t sA = smem_base + (it % 3) * STAGE_BYTES;
        const uint32_t sB = sA + A_BYTES;
#pragma unroll
        for (int kt = 0; kt < 4; kt++) {
            const uint32_t koff = ((uint32_t)(kt * 32 + kseg)) ^ aswz;
            uint32_t a[2][4], bb[2][4];
#pragma unroll
            for (int mt = 0; mt < 2; mt++)
                LDSM_X4(a[mt][0], a[mt][1], a[mt][2], a[mt][3],
                        sA + arow_off + (uint32_t)(mt * 16 * 128) + koff);
#pragma unroll
            for (int pr = 0; pr < 2; pr++)
                LDSM_X4(bb[pr][0], bb[pr][1], bb[pr][2], bb[pr][3],
                        sB + brow_off + (uint32_t)(pr * 16 * 128) + koff);
#pragma unroll
            for (int mt = 0; mt < 2; mt++)
#pragma unroll
                for (int nt = 0; nt < 4; nt++) {
                    const int pr = nt >> 1, sub = nt & 1;
                    MMAF32(facc[mt][nt], a[mt], bb[pr][sub], bb[pr][sub + 2]);
                }
        }
        __syncthreads();
    }

    // ---- phase 2: cross term a*bl, f16 accumulate ----
    for (int it = NPH1; it < NKITER; it++) {
        CP_WAIT1();
        __syncthreads();
        if (it + 2 < NKITER) load_stage((it + 2) % 3, (it + 2) * BK);
        else                 CP_COMMIT();
        const uint32_t sA = smem_base + (it % 3) * STAGE_BYTES;
        const uint32_t sB = sA + A_BYTES;
#pragma unroll
        for (int kt = 0; kt < 4; kt++) {
            const uint32_t koff = ((uint32_t)(kt * 32 + kseg)) ^ aswz;
            uint32_t a[2][4], bb[2][4];
#pragma unroll
            for (int mt = 0; mt < 2; mt++)
                LDSM_X4(a[mt][0], a[mt][1], a[mt][2], a[mt][3],
                        sA + arow_off + (uint32_t)(mt * 16 * 128) + koff);
#pragma unroll
            for (int pr = 0; pr < 2; pr++)
                LDSM_X4(bb[pr][0], bb[pr][1], bb[pr][2], bb[pr][3],
                        sB + brow_off + (uint32_t)(pr * 16 * 128) + koff);
#pragma unroll
            for (int mt = 0; mt < 2; mt++)
#pragma unroll
                for (int nt = 0; nt < 4; nt++) {
                    const int pr = nt >> 1, sub = nt & 1;
                    MMAF16(hacc[mt][nt], a[mt], bb[pr][sub], bb[pr][sub + 2]);
                }
        }
        __syncthreads();
    }

    const int rbase = block_row + wm * 32 + (lane >> 2);
    const int cbase = block_col + wn * 32 + (lane & 3) * 2;

#pragma unroll
    for (int mt = 0; mt < 2; mt++) {
#pragma unroll
        for (int nt = 0; nt < 4; nt++) {
            const float2 cx01 = __half22float2(*reinterpret_cast<__half2*>(&hacc[mt][nt][0]));
            const float2 cx23 = __half22float2(*reinterpret_cast<__half2*>(&hacc[mt][nt][1]));
            const int col = cbase + nt * 8;
            const float bx = bias[col];
            const float by = bias[col + 1];
            const float r00 = facc[mt][nt][0] + cx01.x + bx;
            const float r01 = facc[mt][nt][1] + cx01.y + by;
            const float r10 = facc[mt][nt][2] + cx23.x + bx;
            const float r11 = facc[mt][nt][3] + cx23.y + by;
            if (mode == 0) {
                const int r0 = rbase + mt * 16;
                float2 o0 = { r00, r01 };
                float2 o1 = { r10, r11 };
                *(float2*)(C + (size_t)r0 * N + col)       = o0;
                *(float2*)(C + (size_t)(r0 + 8) * N + col) = o1;
            } else {
                const int part = col >> 10;          // CTA-uniform (BN=64, head-aligned)
                const int hh   = (col >> 6) & 15;
                const int dd   = col & 63;
#pragma unroll
                for (int rr = 0; rr < 2; rr++) {
                    const int r = rbase + mt * 16 + rr * 8;
                    float v0 = rr ? r10 : r00;
                    float v1 = rr ? r11 : r01;
                    const size_t off =
                        (((size_t)((r >> 11) * 16 + hh)) * SEQ + (r & 2047)) * 64 + dd;
                    if (part == 0) {
                        v0 *= QSCALE; v1 *= QSCALE;
                        *(uint32_t*)(qh + off) = pack2h(__float2half(v0), __float2half(v1));
                    } else {
                        __half* dh = part == 1 ? kh : vh;
                        __half* dl = part == 1 ? kl : vl;
                        const __half h0 = __float2half(v0);
                        const __half h1 = __float2half(v1);
                        *(uint32_t*)(dh + off) = pack2h(h0, h1);
                        *(uint32_t*)(dl + off) =
                            pack2h(__float2half(v0 - __half2float(h0)),
                                   __float2half(v1 - __half2float(h1)));
                    }
                }
            }
        }
    }
}

// ---------------------------------------------------------------------------
// HMMA causal flash attention, fp16-fed, 2-stage cp.async pipeline,
// 2 CTAs/SM for cross-CTA softmax/MMA overlap.
// One CTA = 128 queries of one (b,h); 8 warps x 16 rows; 64-key tiles.
// 2-pass: Q and P single fp16 limb; K and V split hi/lo.
// Main terms f32-acc; cross terms (qh*kl, ph*vl) f16-acc per tile, folded.
// Output written as stacked fp16 [a|a] rows of g_as.
// smem: QH 16K | 2 stages x {KH,KL,VH,VL 8K each} = 80KB (+pad)
// ---------------------------------------------------------------------------
#define KV_STAGE_BYTES 32768
#define ATTN_SMEM (16384 + 2 * KV_STAGE_BYTES + 128)

__global__ __launch_bounds__(256, 2) void attn_mma_kernel(
    const __half* __restrict__ qh_g,
    const __half* __restrict__ kh_g, const __half* __restrict__ kl_g,
    const __half* __restrict__ vh_g, const __half* __restrict__ vl_g,
    __half* __restrict__ outs)
{
    extern __shared__ char sm[];
    const uint32_t base = (smem_u32(sm) + 127u) & ~127u;
    const uint32_t sQH = base;
    const uint32_t kvbase = base + 16384;

    const int tid  = threadIdx.x;
    const int lane = tid & 31;
    const int wid  = tid >> 5;
    const int qb   = 15 - (int)blockIdx.x;     // heavy blocks first
    const int bh   = blockIdx.y;
    const int b    = bh >> 4;
    const int h    = bh & 15;
    const size_t hrow = (size_t)bh * SEQ;

    // ---- Q tile cp.async (joins group 0) ----
#pragma unroll
    for (int i = 0; i < 4; i++) {
        const int s   = i * 256 + tid;
        const int row = s >> 3;
        const int ch  = s & 7;
        const uint32_t sw = (uint32_t)(ch * 16) ^ (uint32_t)((row & 7) << 4);
        const size_t gofs = (hrow + qb * 128 + row) * 64 + ch * 8;
        cp_async16(sQH + row * 128 + sw, qh_g + gofs);
    }

    auto load_kv = [&](int stage, int k0) {
        const uint32_t sb = kvbase + stage * KV_STAGE_BYTES;
#pragma unroll
        for (int i = 0; i < 2; i++) {
            const int s   = i * 256 + tid;
            const int row = s >> 3;
            const int ch  = s & 7;
            const uint32_t sw = (uint32_t)(ch * 16) ^ (uint32_t)((row & 7) << 4);
            const uint32_t so = row * 128 + sw;
            const size_t gofs = (hrow + k0 + row) * 64 + ch * 8;
            cp_async16(sb + so,         kh_g + gofs);
            cp_async16(sb + 8192 + so,  kl_g + gofs);
            cp_async16(sb + 16384 + so, vh_g + gofs);
            cp_async16(sb + 24576 + so, vl_g + gofs);
        }
        CP_COMMIT();
    };

    const int nk = (qb + 1) * 2;
    load_kv(0, 0);                 // group 0 (with Q)

    float acc_o[8][4];
#pragma unroll
    for (int nt = 0; nt < 8; nt++)
#pragma unroll
        for (int r = 0; r < 4; r++) acc_o[nt][r] = 0.0f;
    float m0 = -1e30f, m1 = -1e30f, l0 = 0.0f, l1 = 0.0f;

    const int r0      = lane >> 2;
    const int qrow_w  = qb * 128 + wid * 16;
    const int qg0     = qrow_w + r0;

    const int a_r = wid * 16 + (lane & 15);
    const int a_c = (lane >> 4) * 16;
    const uint32_t a_row_off = (uint32_t)(a_r * 128);
    const uint32_t a_sw = (uint32_t)((a_r & 7) << 4);
    const int g      = lane >> 3;
    const int br_off = lane & 7;

    for (int t = 0; t < nk; t++) {
        const int k0 = t * 64;
        // issue next stage's load (buffer consumed two iterations ago;
        // end-of-iteration barrier below guarantees it is free)
        if (t + 1 < nk) load_kv((t + 1) & 1, (t + 1) * 64);
        else            CP_COMMIT();
        CP_WAIT1();                // stage t's group complete
        __syncthreads();

        const uint32_t st  = kvbase + (t & 1) * KV_STAGE_BYTES;
        const uint32_t sKH = st;
        const uint32_t sKL = st + 8192;
        const uint32_t sVH = st + 16384;
        const uint32_t sVL = st + 24576;

        // ---- S = Q K^T: main (qh*kh) f32, cross (qh*kl) f16 ----
        float s[8][4];
        uint32_t scx[8][2];
#pragma unroll
        for (int nt = 0; nt < 8; nt++) {
#pragma unroll
            for (int r = 0; r < 4; r++) s[nt][r] = 0.0f;
            scx[nt][0] = 0u; scx[nt][1] = 0u;
        }

#pragma unroll
        for (int kc = 0; kc < 4; kc++) {
            uint32_t qhf[4];
            const uint32_t qoff = ((uint32_t)(kc * 32 + a_c)) ^ a_sw;
            LDSM_X4(qhf[0], qhf[1], qhf[2], qhf[3], sQH + a_row_off + qoff);
#pragma unroll
            for (int np = 0; np < 4; np++) {
                const int brow = np * 16 + ((g & 2) << 2) + br_off;
                const uint32_t boff = ((uint32_t)(kc * 32 + ((g & 1) << 4)))
                                    ^ (uint32_t)((brow & 7) << 4);
                const uint32_t rb = (uint32_t)(brow * 128) + boff;
                uint32_t kh0, kh1, kh2, kh3, kl0, kl1, kl2, kl3;
                LDSM_X4(kh0, kh1, kh2, kh3, sKH + rb);
                LDSM_X4(kl0, kl1, kl2, kl3, sKL + rb);
                MMAF32(s[2 * np],     qhf, kh0, kh1);
                MMAF32(s[2 * np + 1], qhf, kh2, kh3);
                MMAF16(scx[2 * np],     qhf, kl0, kl1);
                MMAF16(scx[2 * np + 1], qhf, kl2, kl3);
            }
        }
        // fold cross terms
#pragma unroll
        for (int nt = 0; nt < 8; nt++) {
            const float2 cA = __half22float2(*reinterpret_cast<__half2*>(&scx[nt][0]));
            const float2 cB = __half22float2(*reinterpret_cast<__half2*>(&scx[nt][1]));
            s[nt][0] += cA.x; s[nt][1] += cA.y;
            s[nt][2] += cB.x; s[nt][3] += cB.y;
        }

        // ---- causal mask ----
        if (k0 + 63 > qrow_w) {
#pragma unroll
            for (int nt = 0; nt < 8; nt++) {
                const int kg0 = k0 + nt * 8 + 2 * (lane & 3);
                if (kg0     > qg0)     s[nt][0] = -1e30f;
                if (kg0 + 1 > qg0)     s[nt][1] = -1e30f;
                if (kg0     > qg0 + 8) s[nt][2] = -1e30f;
                if (kg0 + 1 > qg0 + 8) s[nt][3] = -1e30f;
            }
        }

        // ---- online softmax (base-2) ----
        float rx0 = -1e30f, rx1 = -1e30f;
#pragma unroll
        for (int nt = 0; nt < 8; nt++) {
            rx0 = fmaxf(rx0, fmaxf(s[nt][0], s[nt][1]));
            rx1 = fmaxf(rx1, fmaxf(s[nt][2], s[nt][3]));
        }
        rx0 = fmaxf(rx0, __shfl_xor_sync(0xffffffffu, rx0, 1));
        rx0 = fmaxf(rx0, __shfl_xor_sync(0xffffffffu, rx0, 2));
        rx1 = fmaxf(rx1, __shfl_xor_sync(0xffffffffu, rx1, 1));
        rx1 = fmaxf(rx1, __shfl_xor_sync(0xffffffffu, rx1, 2));
        const float mn0 = fmaxf(m0, rx0);
        const float mn1 = fmaxf(m1, rx1);
        const float sc0 = fexp2(m0 - mn0);
        const float sc1 = fexp2(m1 - mn1);
        m0 = mn0; m1 = mn1;
        l0 *= sc0; l1 *= sc1;
#pragma unroll
        for (int nt = 0; nt < 8; nt++) {
            acc_o[nt][0] *= sc0; acc_o[nt][1] *= sc0;
            acc_o[nt][2] *= sc1; acc_o[nt][3] *= sc1;
        }

        uint32_t ph[4][4];
#pragma unroll
        for (int nt = 0; nt < 8; nt++) {
            const float p0 = fexp2(s[nt][0] - m0);
            const float p1 = fexp2(s[nt][1] - m0);
            const float p2 = fexp2(s[nt][2] - m1);
            const float p3 = fexp2(s[nt][3] - m1);
            l0 += p0 + p1;
            l1 += p2 + p3;
            const int kc = nt >> 1;
            const int rr = (nt & 1) * 2;
            ph[kc][rr]     = pack2h(__float2half(p0), __float2half(p1));
            ph[kc][rr + 1] = pack2h(__float2half(p2), __float2half(p3));
        }

        // ---- O += P V: main (ph*vh) f32, cross (ph*vl) f16, folded ----
        uint32_t ocx[8][2];
#pragma unroll
        for (int nt = 0; nt < 8; nt++) { ocx[nt][0] = 0u; ocx[nt][1] = 0u; }
#pragma unroll
        for (int kc = 0; kc < 4; kc++) {
#pragma unroll
            for (int np = 0; np < 4; np++) {
                const int vrow = kc * 16 + ((g & 1) << 3) + br_off;
                const uint32_t voff = ((uint32_t)(np * 32 + ((g & 2) << 3)))
                                    ^ (uint32_t)((vrow & 7) << 4);
                const uint32_t rv = (uint32_t)(vrow * 128) + voff;
                uint32_t vh0, vh1, vh2, vh3, vl0, vl1, vl2, vl3;
                LDSM_X4T(vh0, vh1, vh2, vh3, sVH + rv);
                LDSM_X4T(vl0, vl1, vl2, vl3, sVL + rv);
                MMAF32(acc_o[2 * np],     ph[kc], vh0, vh1);
                MMAF32(acc_o[2 * np + 1], ph[kc], vh2, vh3);
                MMAF16(ocx[2 * np],     ph[kc], vl0, vl1);
                MMAF16(ocx[2 * np + 1], ph[kc], vl2, vl3);
            }
        }
#pragma unroll
        for (int nt = 0; nt < 8; nt++) {
            const float2 cA = __half22float2(*reinterpret_cast<__half2*>(&ocx[nt][0]));
            const float2 cB = __half22float2(*reinterpret_cast<__half2*>(&ocx[nt][1]));
            acc_o[nt][0] += cA.x; acc_o[nt][1] += cA.y;
            acc_o[nt][2] += cB.x; acc_o[nt][3] += cB.y;
        }
        __syncthreads();   // buffer (t&1) free for the load issued at t+2
    }

    // ---- epilogue: normalize, write stacked fp16 [a|a] rows of g_as ----
    l0 += __shfl_xor_sync(0xffffffffu, l0, 1);
    l0 += __shfl_xor_sync(0xffffffffu, l0, 2);
    l1 += __shfl_xor_sync(0xffffffffu, l1, 1);
    l1 += __shfl_xor_sync(0xffffffffu, l1, 2);
    const float inv0 = 1.0f / l0;
    const float inv1 = 1.0f / l1;

    const size_t row0 = (size_t)(b * SEQ + qg0) * KS;
    const size_t row1 = row0 + 8 * KS;
    const int colbase = h * HD + 2 * (lane & 3);
#pragma unroll
    for (int nt = 0; nt < 8; nt++) {
        const int col = colbase + nt * 8;
        const uint32_t o01 = pack2h(__float2half(acc_o[nt][0] * inv0),
                                    __float2half(acc_o[nt][1] * inv0));
        const uint32_t o23 = pack2h(__float2half(acc_o[nt][2] * inv1),
                                    __float2half(acc_o[nt][3] * inv1));
        *(uint32_t*)(outs + row0 + col)        = o01;
        *(uint32_t*)(outs + row0 + col + 1024) = o01;
        *(uint32_t*)(outs + row1 + col)        = o23;
        *(uint32_t*)(outs + row1 + col + 1024) = o23;
    }
}

// ---------------------------------------------------------------------------
extern "C" void kernel_launch(void* const* d_in, const int* in_sizes, int n_in,
                              void* d_out, int out_size)
{
    const float* x     = (const float*)d_in[0];
    const float* w_qkv = (const float*)d_in[1];
    const float* b_qkv = (const float*)d_in[2];
    const float* w_out = (const float*)d_in[3];
    const float* b_out = (const float*)d_in[4];
    float* out = (float*)d_out;

    __half *as, *wqkvs, *wouts, *qh, *kh, *kl, *vh, *vl;
    cudaGetSymbolAddress((void**)&as,    g_as);
    cudaGetSymbolAddress((void**)&wqkvs, g_wqkv_s);
    cudaGetSymbolAddress((void**)&wouts, g_wout_s);
    cudaGetSymbolAddress((void**)&qh, g_qh);
    cudaGetSymbolAddress((void**)&kh, g_kh);
    cudaGetSymbolAddress((void**)&kl, g_kl);
    cudaGetSymbolAddress((void**)&vh, g_vh);
    cudaGetSymbolAddress((void**)&vl, g_vl);

    cudaFuncSetAttribute(mma_gemm_kernel,
                         cudaFuncAttributeMaxDynamicSharedMemorySize, GEMM_SMEM);
    cudaFuncSetAttribute(attn_mma_kernel,
                         cudaFuncAttributeMaxDynamicSharedMemorySize, ATTN_SMEM);

    // 1) Convert weights (transpose + fp16 hi/lo split, K=2048 stack)
    {
        dim3 grid(QKV_N / 32, HID / 32);
        convert_w_kernel<<<grid, 1024>>>(w_qkv, wqkvs, QKV_N);
    }
    {
        dim3 grid(HID / 32, HID / 32);
        convert_w_kernel<<<grid, 1024>>>(w_out, wouts, HID);
    }
    // 2) Convert x (single limb, duplicated, vectorized)
    convert_act_kernel<<<(MROWS * 256 + 255) / 256, 256>>>(x, as, MROWS);
    // 3) QKV projection -> head-major fp16 Q / hi-lo K,V (mode 1)
    {
        dim3 grid(QKV_N / BN, MROWS / BM);
        mma_gemm_kernel<<<grid, 256, GEMM_SMEM>>>(as, wqkvs, b_qkv, nullptr,
                                                  QKV_N, 1,
                                                  qh, kh, kl, vh, vl);
    }
    // 4) HMMA flash attention (2-pass, 2-stage, 2 CTA/SM) -> stacked fp16 g_as
    {
        dim3 grid(16, BATCH * NHEADS);
        attn_mma_kernel<<<grid, 256, ATTN_SMEM>>>(qh, kh, kl, vh, vl, as);
    }
    // 5) Output projection (mode 0)
    {
        dim3 grid(HID / BN, MROWS / BM);
        mma_gemm_kernel<<<grid, 256, GEMM_SMEM>>>(as, wouts, b_out, out,
                                                  HID, 0,
                                                  nullptr, nullptr, nullptr,
                                                  nullptr, nullptr);
    }
}

// round 11
// speedup vs baseline: 1.1629x; 1.1629x over previous
#include <cuda_runtime.h>
#include <cuda_fp16.h>
#include <cstdint>
#include <math.h>

// Problem constants
#define BATCH   2
#define SEQ     2048
#define HID     1024
#define NHEADS  16
#define HD      64
#define QKV_N   3072
#define MROWS   4096
#define KA      1024          // A (activations): single fp16 limb
#define KB      2048          // B (weights): stacked [bh|bl]

#define QSCALE  0.18033688f   // 0.125 * log2(e)

// ---------------- scratch (device globals; no allocations allowed) ----------
__device__ __half g_as[(size_t)MROWS * KA];            // activations, single limb
__device__ __half g_wqkv_s[(size_t)QKV_N * KB];        // stacked W^T [bh|bl]
__device__ __half g_wout_s[(size_t)HID * KB];
// Head-major fp16 Q (single limb) and hi/lo K/V: [b*16+h][s][64]
#define HM_ELEMS ((size_t)BATCH * NHEADS * SEQ * HD)
__device__ __half g_qh[HM_ELEMS];
__device__ __half g_kh[HM_ELEMS], g_kl[HM_ELEMS];
__device__ __half g_vh[HM_ELEMS], g_vl[HM_ELEMS];

// ---------------- PTX helpers (base ISA only) ----------------
__device__ __forceinline__ uint32_t smem_u32(const void* p) {
    uint32_t a;
    asm("{ .reg .u64 t; cvta.to.shared.u64 t, %1; cvt.u32.u64 %0, t; }" : "=r"(a) : "l"(p));
    return a;
}

__device__ __forceinline__ void cp_async16(uint32_t s, const void* g) {
    asm volatile("cp.async.cg.shared.global [%0], [%1], 16;" :: "r"(s), "l"(g) : "memory");
}
#define CP_COMMIT() asm volatile("cp.async.commit_group;" ::: "memory")
#define CP_WAIT1()  asm volatile("cp.async.wait_group 1;"  ::: "memory")

#define LDSM_X4(R0, R1, R2, R3, ADDR)                                          \
    asm volatile("ldmatrix.sync.aligned.m8n8.x4.shared.b16 {%0,%1,%2,%3}, [%4];" \
                 : "=r"(R0), "=r"(R1), "=r"(R2), "=r"(R3) : "r"(ADDR))

#define LDSM_X4T(R0, R1, R2, R3, ADDR)                                         \
    asm volatile("ldmatrix.sync.aligned.m8n8.x4.trans.shared.b16 {%0,%1,%2,%3}, [%4];" \
                 : "=r"(R0), "=r"(R1), "=r"(R2), "=r"(R3) : "r"(ADDR))

// fp16 inputs, f32 accumulate (main pass)
#define MMAF32(D, A, B0, B1)                                                   \
    asm volatile("mma.sync.aligned.m16n8k16.row.col.f32.f16.f16.f32 "          \
                 "{%0,%1,%2,%3},{%4,%5,%6,%7},{%8,%9},{%0,%1,%2,%3};"          \
                 : "+f"((D)[0]), "+f"((D)[1]), "+f"((D)[2]), "+f"((D)[3])      \
                 : "r"((A)[0]), "r"((A)[1]), "r"((A)[2]), "r"((A)[3]),         \
                   "r"(B0), "r"(B1))

// fp16 inputs, f16 accumulate (cross pass; values ~2^-11 of main)
#define MMAF16(D, A, B0, B1)                                                   \
    asm volatile("mma.sync.aligned.m16n8k16.row.col.f16.f16.f16.f16 "          \
                 "{%0,%1},{%2,%3,%4,%5},{%6,%7},{%0,%1};"                      \
                 : "+r"((D)[0]), "+r"((D)[1])                                  \
                 : "r"((A)[0]), "r"((A)[1]), "r"((A)[2]), "r"((A)[3]),         \
                   "r"(B0), "r"(B1))

// exp2 via MUFU (1 issue slot; ~2 ulp). Huge negatives flush to 0 as needed.
__device__ __forceinline__ float fexp2(float x) {
    float y;
    asm("ex2.approx.f32 %0, %1;" : "=f"(y) : "f"(x));
    return y;
}

__device__ __forceinline__ uint32_t pack2h(__half a, __half b) {
    __half2 t;
    t.x = a; t.y = b;
    return *reinterpret_cast<uint32_t*>(&t);
}

// ---------------------------------------------------------------------------
// Conversion: fp32 activations [R,1024] -> fp16 [R,1024] (single limb)
// ---------------------------------------------------------------------------
__global__ __launch_bounds__(256) void convert_act_kernel(
    const float* __restrict__ in, __half* __restrict__ out, int R)
{
    int idx = blockIdx.x * 256 + threadIdx.x;     // over R*256 float4s
    if (idx >= R * 256) return;
    const float4 v = ((const float4*)in)[idx];
    uint2 h;
    h.x = pack2h(__float2half(v.x), __float2half(v.y));
    h.y = pack2h(__float2half(v.z), __float2half(v.w));
    ((uint2*)out)[idx] = h;
}

// ---------------------------------------------------------------------------
// Conversion + transpose: W fp32 [K=1024, N] -> stacked fp16 [N,2048]=[bh|bl]
// ---------------------------------------------------------------------------
__global__ __launch_bounds__(1024) void convert_w_kernel(
    const float* __restrict__ w, __half* __restrict__ out, int N)
{
    __shared__ float tile[32][33];
    int tx = threadIdx.x & 31;
    int ty = threadIdx.x >> 5;
    int gn = blockIdx.x * 32;
    int gk = blockIdx.y * 32;
    tile[ty][tx] = w[(size_t)(gk + ty) * N + gn + tx];
    __syncthreads();
    float v = tile[tx][ty];
    __half h = __float2half(v);
    __half l = __float2half(v - __half2float(h));
    size_t o = (size_t)(gn + ty) * KB + gk + tx;
    out[o]        = h;
    out[o + 1024] = l;
}

// ---------------------------------------------------------------------------
// HMMA GEMM: C[4096,N] = A[4096,1024] @ (Bh+Bl)[N,1024]^T + bias.
// CTA tile 128x64, 256 threads (8 warps, 4x2), warp tile 32x32.
// 16 K-iterations; per iter: A loaded once, used for Bh (f32-acc) and
// Bl (f16-acc, folded at end). Identical per-accumulator k-order as the
// 2-phase version -> bit-identical results.
// mode 0: fp32 C out.  mode 1: QKV epilogue -> fp16 Q (single) / K,V hi-lo.
// ---------------------------------------------------------------------------
#define BM 128
#define BN 64
#define BK 64
#define NKITER (KA / BK)                   // 16
#define A_BYTES (BM * 128)                 // 16 KB
#define B_BYTES (BN * 128)                 // 8 KB
#define STAGE_BYTES (A_BYTES + 2 * B_BYTES)// 32 KB (A, Bh, Bl)
#define GEMM_SMEM (3 * STAGE_BYTES + 128)

__global__ __launch_bounds__(256, 2) void mma_gemm_kernel(
    const __half* __restrict__ As, const __half* __restrict__ Bs,
    const float* __restrict__ bias, float* __restrict__ C, int N, int mode,
    __half* __restrict__ qh,
    __half* __restrict__ kh, __half* __restrict__ kl,
    __half* __restrict__ vh, __half* __restrict__ vl)
{
    extern __shared__ char dsmem[];
    const uint32_t smem_base = (smem_u32(dsmem) + 127u) & ~127u;

    const int tid  = threadIdx.x;
    const int wid  = tid >> 5;
    const int lane = tid & 31;
    const int wm   = wid >> 1;     // 0..3 (32-row slab)
    const int wn   = wid & 1;      // 0..1 (32-col slab)

    const int block_row = blockIdx.y * BM;
    const int block_col = blockIdx.x * BN;

    const __half* Abase = As + (size_t)block_row * KA;
    const __half* Bbase = Bs + (size_t)block_col * KB;

    auto load_stage = [&](int stage, int kc) {
        const uint32_t sA  = smem_base + stage * STAGE_BYTES;
        const uint32_t sBh = sA + A_BYTES;
        const uint32_t sBl = sBh + B_BYTES;
#pragma unroll
        for (int i = 0; i < 4; i++) {       // A: 1024 16B segs
            const int s   = i * 256 + tid;
            const int row = s >> 3;
            const int ch  = s & 7;
            const uint32_t sw = (uint32_t)(ch * 16) ^ (uint32_t)((row & 7) << 4);
            cp_async16(sA + row * 128 + sw, Abase + (size_t)row * KA + kc + ch * 8);
        }
#pragma unroll
        for (int i = 0; i < 2; i++) {       // Bh + Bl: 512 segs each
            const int s   = i * 256 + tid;
            const int row = s >> 3;
            const int ch  = s & 7;
            const uint32_t sw = (uint32_t)(ch * 16) ^ (uint32_t)((row & 7) << 4);
            const __half* bp = Bbase + (size_t)row * KB + kc + ch * 8;
            cp_async16(sBh + row * 128 + sw, bp);
            cp_async16(sBl + row * 128 + sw, bp + 1024);
        }
        CP_COMMIT();
    };

    float    facc[2][4][4];
    uint32_t hacc[2][4][2];
#pragma unroll
    for (int mt = 0; mt < 2; mt++)
#pragma unroll
        for (int nt = 0; nt < 4; nt++) {
#pragma unroll
            for (int r = 0; r < 4; r++) facc[mt][nt][r] = 0.0f;
            hacc[mt][nt][0] = 0u; hacc[mt][nt][1] = 0u;
        }

    load_stage(0, 0);
    load_stage(1, BK);

    const int lrow  = lane & 15;
    const int kseg  = (lane >> 4) * 16;
    const uint32_t arow_off = (uint32_t)(wm * 32 + lrow) * 128;
    const uint32_t brow_off = (uint32_t)(wn * 32 + lrow) * 128;
    const uint32_t aswz = (uint32_t)((lrow & 7) << 4);

    for (int it = 0; it < NKITER; it++) {
        CP_WAIT1();
        __syncthreads();
        if (it + 2 < NKITER) load_stage((it + 2) % 3, (it + 2) * BK);
        else                 CP_COMMIT();
        const uint32_t sA  = smem_base + (it % 3) * STAGE_BYTES;
        const uint32_t sBh = sA + A_BYTES;
        const uint32_t sBl = sBh + B_BYTES;
#pragma unroll
        for (int kt = 0; kt < 4; kt++) {
            const uint32_t koff = ((uint32_t)(kt * 32 + kseg)) ^ aswz;
            uint32_t a[2][4], bh_[2][4], bl_[2][4];
#pragma unroll
            for (int mt = 0; mt < 2; mt++)
                LDSM_X4(a[mt][0], a[mt][1], a[mt][2], a[mt][3],
                        sA + arow_off + (uint32_t)(mt * 16 * 128) + koff);
#pragma unroll
            for (int pr = 0; pr < 2; pr++) {
                const uint32_t bo = brow_off + (uint32_t)(pr * 16 * 128) + koff;
                LDSM_X4(bh_[pr][0], bh_[pr][1], bh_[pr][2], bh_[pr][3], sBh + bo);
                LDSM_X4(bl_[pr][0], bl_[pr][1], bl_[pr][2], bl_[pr][3], sBl + bo);
            }
#pragma unroll
            for (int mt = 0; mt < 2; mt++)
#pragma unroll
                for (int nt = 0; nt < 4; nt++) {
                    const int pr = nt >> 1, sub = nt & 1;
                    MMAF32(facc[mt][nt], a[mt], bh_[pr][sub], bh_[pr][sub + 2]);
                    MMAF16(hacc[mt][nt], a[mt], bl_[pr][sub], bl_[pr][sub + 2]);
                }
        }
        __syncthreads();
    }

    const int rbase = block_row + wm * 32 + (lane >> 2);
    const int cbase = block_col + wn * 32 + (lane & 3) * 2;

#pragma unroll
    for (int mt = 0; mt < 2; mt++) {
#pragma unroll
        for (int nt = 0; nt < 4; nt++) {
            const float2 cx01 = __half22float2(*reinterpret_cast<__half2*>(&hacc[mt][nt][0]));
            const float2 cx23 = __half22float2(*reinterpret_cast<__half2*>(&hacc[mt][nt][1]));
            const int col = cbase + nt * 8;
            const float bx = bias[col];
            const float by = bias[col + 1];
            const float r00 = facc[mt][nt][0] + cx01.x + bx;
            const float r01 = facc[mt][nt][1] + cx01.y + by;
            const float r10 = facc[mt][nt][2] + cx23.x + bx;
            const float r11 = facc[mt][nt][3] + cx23.y + by;
            if (mode == 0) {
                const int r0 = rbase + mt * 16;
                float2 o0 = { r00, r01 };
                float2 o1 = { r10, r11 };
                *(float2*)(C + (size_t)r0 * N + col)       = o0;
                *(float2*)(C + (size_t)(r0 + 8) * N + col) = o1;
            } else {
                const int part = col >> 10;          // CTA-uniform (BN=64, head-aligned)
                const int hh   = (col >> 6) & 15;
                const int dd   = col & 63;
#pragma unroll
                for (int rr = 0; rr < 2; rr++) {
                    const int r = rbase + mt * 16 + rr * 8;
                    float v0 = rr ? r10 : r00;
                    float v1 = rr ? r11 : r01;
                    const size_t off =
                        (((size_t)((r >> 11) * 16 + hh)) * SEQ + (r & 2047)) * 64 + dd;
                    if (part == 0) {
                        v0 *= QSCALE; v1 *= QSCALE;
                        *(uint32_t*)(qh + off) = pack2h(__float2half(v0), __float2half(v1));
                    } else {
                        __half* dh = part == 1 ? kh : vh;
                        __half* dl = part == 1 ? kl : vl;
                        const __half h0 = __float2half(v0);
                        const __half h1 = __float2half(v1);
                        *(uint32_t*)(dh + off) = pack2h(h0, h1);
                        *(uint32_t*)(dl + off) =
                            pack2h(__float2half(v0 - __half2float(h0)),
                                   __float2half(v1 - __half2float(h1)));
                    }
                }
            }
        }
    }
}

// ---------------------------------------------------------------------------
// HMMA causal flash attention, fp16-fed, 2-stage cp.async pipeline,
// 2 CTAs/SM. One CTA = 128 queries of one (b,h); 8 warps x 16 rows;
// 64-key tiles. Q/P single limb; K/V split hi/lo; MUFU exp2 softmax.
// Output: fp16 [R,1024] rows of g_as.
// smem: QH 16K | 2 stages x {KH,KL,VH,VL 8K each} = 80KB (+pad)
// ---------------------------------------------------------------------------
#define KV_STAGE_BYTES 32768
#define ATTN_SMEM (16384 + 2 * KV_STAGE_BYTES + 128)

__global__ __launch_bounds__(256, 2) void attn_mma_kernel(
    const __half* __restrict__ qh_g,
    const __half* __restrict__ kh_g, const __half* __restrict__ kl_g,
    const __half* __restrict__ vh_g, const __half* __restrict__ vl_g,
    __half* __restrict__ outs)
{
    extern __shared__ char sm[];
    const uint32_t base = (smem_u32(sm) + 127u) & ~127u;
    const uint32_t sQH = base;
    const uint32_t kvbase = base + 16384;

    const int tid  = threadIdx.x;
    const int lane = tid & 31;
    const int wid  = tid >> 5;
    const int qb   = 15 - (int)blockIdx.x;     // heavy blocks first
    const int bh   = blockIdx.y;
    const int b    = bh >> 4;
    const int h    = bh & 15;
    const size_t hrow = (size_t)bh * SEQ;

    // ---- Q tile cp.async (joins group 0) ----
#pragma unroll
    for (int i = 0; i < 4; i++) {
        const int s   = i * 256 + tid;
        const int row = s >> 3;
        const int ch  = s & 7;
        const uint32_t sw = (uint32_t)(ch * 16) ^ (uint32_t)((row & 7) << 4);
        const size_t gofs = (hrow + qb * 128 + row) * 64 + ch * 8;
        cp_async16(sQH + row * 128 + sw, qh_g + gofs);
    }

    auto load_kv = [&](int stage, int k0) {
        const uint32_t sb = kvbase + stage * KV_STAGE_BYTES;
#pragma unroll
        for (int i = 0; i < 2; i++) {
            const int s   = i * 256 + tid;
            const int row = s >> 3;
            const int ch  = s & 7;
            const uint32_t sw = (uint32_t)(ch * 16) ^ (uint32_t)((row & 7) << 4);
            const uint32_t so = row * 128 + sw;
            const size_t gofs = (hrow + k0 + row) * 64 + ch * 8;
            cp_async16(sb + so,         kh_g + gofs);
            cp_async16(sb + 8192 + so,  kl_g + gofs);
            cp_async16(sb + 16384 + so, vh_g + gofs);
            cp_async16(sb + 24576 + so, vl_g + gofs);
        }
        CP_COMMIT();
    };

    const int nk = (qb + 1) * 2;
    load_kv(0, 0);                 // group 0 (with Q)

    float acc_o[8][4];
#pragma unroll
    for (int nt = 0; nt < 8; nt++)
#pragma unroll
        for (int r = 0; r < 4; r++) acc_o[nt][r] = 0.0f;
    float m0 = -1e30f, m1 = -1e30f, l0 = 0.0f, l1 = 0.0f;

    const int r0      = lane >> 2;
    const int qrow_w  = qb * 128 + wid * 16;
    const int qg0     = qrow_w + r0;

    const int a_r = wid * 16 + (lane & 15);
    const int a_c = (lane >> 4) * 16;
    const uint32_t a_row_off = (uint32_t)(a_r * 128);
    const uint32_t a_sw = (uint32_t)((a_r & 7) << 4);
    const int g      = lane >> 3;
    const int br_off = lane & 7;

    for (int t = 0; t < nk; t++) {
        const int k0 = t * 64;
        if (t + 1 < nk) load_kv((t + 1) & 1, (t + 1) * 64);
        else            CP_COMMIT();
        CP_WAIT1();                // stage t's group complete
        __syncthreads();

        const uint32_t st  = kvbase + (t & 1) * KV_STAGE_BYTES;
        const uint32_t sKH = st;
        const uint32_t sKL = st + 8192;
        const uint32_t sVH = st + 16384;
        const uint32_t sVL = st + 24576;

        // ---- S = Q K^T: main (qh*kh) f32, cross (qh*kl) f16 ----
        float s[8][4];
        uint32_t scx[8][2];
#pragma unroll
        for (int nt = 0; nt < 8; nt++) {
#pragma unroll
            for (int r = 0; r < 4; r++) s[nt][r] = 0.0f;
            scx[nt][0] = 0u; scx[nt][1] = 0u;
        }

#pragma unroll
        for (int kc = 0; kc < 4; kc++) {
            uint32_t qhf[4];
            const uint32_t qoff = ((uint32_t)(kc * 32 + a_c)) ^ a_sw;
            LDSM_X4(qhf[0], qhf[1], qhf[2], qhf[3], sQH + a_row_off + qoff);
#pragma unroll
            for (int np = 0; np < 4; np++) {
                const int brow = np * 16 + ((g & 2) << 2) + br_off;
                const uint32_t boff = ((uint32_t)(kc * 32 + ((g & 1) << 4)))
                                    ^ (uint32_t)((brow & 7) << 4);
                const uint32_t rb = (uint32_t)(brow * 128) + boff;
                uint32_t kh0, kh1, kh2, kh3, kl0, kl1, kl2, kl3;
                LDSM_X4(kh0, kh1, kh2, kh3, sKH + rb);
                LDSM_X4(kl0, kl1, kl2, kl3, sKL + rb);
                MMAF32(s[2 * np],     qhf, kh0, kh1);
                MMAF32(s[2 * np + 1], qhf, kh2, kh3);
                MMAF16(scx[2 * np],     qhf, kl0, kl1);
                MMAF16(scx[2 * np + 1], qhf, kl2, kl3);
            }
        }
        // fold cross terms
#pragma unroll
        for (int nt = 0; nt < 8; nt++) {
            const float2 cA = __half22float2(*reinterpret_cast<__half2*>(&scx[nt][0]));
            const float2 cB = __half22float2(*reinterpret_cast<__half2*>(&scx[nt][1]));
            s[nt][0] += cA.x; s[nt][1] += cA.y;
            s[nt][2] += cB.x; s[nt][3] += cB.y;
        }

        // ---- causal mask ----
        if (k0 + 63 > qrow_w) {
#pragma unroll
            for (int nt = 0; nt < 8; nt++) {
                const int kg0 = k0 + nt * 8 + 2 * (lane & 3);
                if (kg0     > qg0)     s[nt][0] = -1e30f;
                if (kg0 + 1 > qg0)     s[nt][1] = -1e30f;
                if (kg0     > qg0 + 8) s[nt][2] = -1e30f;
                if (kg0 + 1 > qg0 + 8) s[nt][3] = -1e30f;
            }
        }

        // ---- online softmax (base-2, MUFU exp2) ----
        float rx0 = -1e30f, rx1 = -1e30f;
#pragma unroll
        for (int nt = 0; nt < 8; nt++) {
            rx0 = fmaxf(rx0, fmaxf(s[nt][0], s[nt][1]));
            rx1 = fmaxf(rx1, fmaxf(s[nt][2], s[nt][3]));
        }
        rx0 = fmaxf(rx0, __shfl_xor_sync(0xffffffffu, rx0, 1));
        rx0 = fmaxf(rx0, __shfl_xor_sync(0xffffffffu, rx0, 2));
        rx1 = fmaxf(rx1, __shfl_xor_sync(0xffffffffu, rx1, 1));
        rx1 = fmaxf(rx1, __shfl_xor_sync(0xffffffffu, rx1, 2));
        const float mn0 = fmaxf(m0, rx0);
        const float mn1 = fmaxf(m1, rx1);
        const float sc0 = fexp2(m0 - mn0);
        const float sc1 = fexp2(m1 - mn1);
        m0 = mn0; m1 = mn1;
        l0 *= sc0; l1 *= sc1;
#pragma unroll
        for (int nt = 0; nt < 8; nt++) {
            acc_o[nt][0] *= sc0; acc_o[nt][1] *= sc0;
            acc_o[nt][2] *= sc1; acc_o[nt][3] *= sc1;
        }

        uint32_t ph[4][4];
#pragma unroll
        for (int nt = 0; nt < 8; nt++) {
            const float p0 = fexp2(s[nt][0] - m0);
            const float p1 = fexp2(s[nt][1] - m0);
            const float p2 = fexp2(s[nt][2] - m1);
            const float p3 = fexp2(s[nt][3] - m1);
            l0 += p0 + p1;
            l1 += p2 + p3;
            const int kc = nt >> 1;
            const int rr = (nt & 1) * 2;
            ph[kc][rr]     = pack2h(__float2half(p0), __float2half(p1));
            ph[kc][rr + 1] = pack2h(__float2half(p2), __float2half(p3));
        }

        // ---- O += P V: main (ph*vh) f32, cross (ph*vl) f16, folded ----
        uint32_t ocx[8][2];
#pragma unroll
        for (int nt = 0; nt < 8; nt++) { ocx[nt][0] = 0u; ocx[nt][1] = 0u; }
#pragma unroll
        for (int kc = 0; kc < 4; kc++) {
#pragma unroll
            for (int np = 0; np < 4; np++) {
                const int vrow = kc * 16 + ((g & 1) << 3) + br_off;
                const uint32_t voff = ((uint32_t)(np * 32 + ((g & 2) << 3)))
                                    ^ (uint32_t)((vrow & 7) << 4);
                const uint32_t rv = (uint32_t)(vrow * 128) + voff;
                uint32_t vh0, vh1, vh2, vh3, vl0, vl1, vl2, vl3;
                LDSM_X4T(vh0, vh1, vh2, vh3, sVH + rv);
                LDSM_X4T(vl0, vl1, vl2, vl3, sVL + rv);
                MMAF32(acc_o[2 * np],     ph[kc], vh0, vh1);
                MMAF32(acc_o[2 * np + 1], ph[kc], vh2, vh3);
                MMAF16(ocx[2 * np],     ph[kc], vl0, vl1);
                MMAF16(ocx[2 * np + 1], ph[kc], vl2, vl3);
            }
        }
#pragma unroll
        for (int nt = 0; nt < 8; nt++) {
            const float2 cA = __half22float2(*reinterpret_cast<__half2*>(&ocx[nt][0]));
            const float2 cB = __half22float2(*reinterpret_cast<__half2*>(&ocx[nt][1]));
            acc_o[nt][0] += cA.x; acc_o[nt][1] += cA.y;
            acc_o[nt][2] += cB.x; acc_o[nt][3] += cB.y;
        }
        __syncthreads();   // buffer (t&1) free for the load issued at t+2
    }

    // ---- epilogue: normalize, write fp16 [R,1024] rows of g_as ----
    l0 += __shfl_xor_sync(0xffffffffu, l0, 1);
    l0 += __shfl_xor_sync(0xffffffffu, l0, 2);
    l1 += __shfl_xor_sync(0xffffffffu, l1, 1);
    l1 += __shfl_xor_sync(0xffffffffu, l1, 2);
    const float inv0 = 1.0f / l0;
    const float inv1 = 1.0f / l1;

    const size_t row0 = (size_t)(b * SEQ + qg0) * KA;
    const size_t row1 = row0 + 8 * KA;
    const int colbase = h * HD + 2 * (lane & 3);
#pragma unroll
    for (int nt = 0; nt < 8; nt++) {
        const int col = colbase + nt * 8;
        const uint32_t o01 = pack2h(__float2half(acc_o[nt][0] * inv0),
                                    __float2half(acc_o[nt][1] * inv0));
        const uint32_t o23 = pack2h(__float2half(acc_o[nt][2] * inv1),
                                    __float2half(acc_o[nt][3] * inv1));
        *(uint32_t*)(outs + row0 + col) = o01;
        *(uint32_t*)(outs + row1 + col) = o23;
    }
}

// ---------------------------------------------------------------------------
extern "C" void kernel_launch(void* const* d_in, const int* in_sizes, int n_in,
                              void* d_out, int out_size)
{
    const float* x     = (const float*)d_in[0];
    const float* w_qkv = (const float*)d_in[1];
    const float* b_qkv = (const float*)d_in[2];
    const float* w_out = (const float*)d_in[3];
    const float* b_out = (const float*)d_in[4];
    float* out = (float*)d_out;

    __half *as, *wqkvs, *wouts, *qh, *kh, *kl, *vh, *vl;
    cudaGetSymbolAddress((void**)&as,    g_as);
    cudaGetSymbolAddress((void**)&wqkvs, g_wqkv_s);
    cudaGetSymbolAddress((void**)&wouts, g_wout_s);
    cudaGetSymbolAddress((void**)&qh, g_qh);
    cudaGetSymbolAddress((void**)&kh, g_kh);
    cudaGetSymbolAddress((void**)&kl, g_kl);
    cudaGetSymbolAddress((void**)&vh, g_vh);
    cudaGetSymbolAddress((void**)&vl, g_vl);

    cudaFuncSetAttribute(mma_gemm_kernel,
                         cudaFuncAttributeMaxDynamicSharedMemorySize, GEMM_SMEM);
    cudaFuncSetAttribute(attn_mma_kernel,
                         cudaFuncAttributeMaxDynamicSharedMemorySize, ATTN_SMEM);

    // 1) Convert weights (transpose + fp16 hi/lo split)
    {
        dim3 grid(QKV_N / 32, HID / 32);
        convert_w_kernel<<<grid, 1024>>>(w_qkv, wqkvs, QKV_N);
    }
    {
        dim3 grid(HID / 32, HID / 32);
        convert_w_kernel<<<grid, 1024>>>(w_out, wouts, HID);
    }
    // 2) Convert x (single limb)
    convert_act_kernel<<<(MROWS * 256 + 255) / 256, 256>>>(x, as, MROWS);
    // 3) QKV projection -> head-major fp16 Q / hi-lo K,V (mode 1)
    {
        dim3 grid(QKV_N / BN, MROWS / BM);
        mma_gemm_kernel<<<grid, 256, GEMM_SMEM>>>(as, wqkvs, b_qkv, nullptr,
                                                  QKV_N, 1,
                                                  qh, kh, kl, vh, vl);
    }
    // 4) HMMA flash attention -> fp16 g_as
    {
        dim3 grid(16, BATCH * NHEADS);
        attn_mma_kernel<<<grid, 256, ATTN_SMEM>>>(qh, kh, kl, vh, vl, as);
    }
    // 5) Output projection (mode 0)
    {
        dim3 grid(HID / BN, MROWS / BM);
        mma_gemm_kernel<<<grid, 256, GEMM_SMEM>>>(as, wouts, b_out, out,
                                                  HID, 0,
                                                  nullptr, nullptr, nullptr,
                                                  nullptr, nullptr);
    }
}

// round 12
// speedup vs baseline: 1.1690x; 1.0053x over previous
#include <cuda_runtime.h>
#include <cuda_fp16.h>
#include <cstdint>
#include <math.h>

// Problem constants
#define BATCH   2
#define SEQ     2048
#define HID     1024
#define NHEADS  16
#define HD      64
#define QKV_N   3072
#define MROWS   4096
#define KA      1024          // A (activations): single fp16 limb
#define KB      2048          // B (weights): stacked [bh|bl]

#define QSCALE  0.18033688f   // 0.125 * log2(e)

// ---------------- scratch (device globals; no allocations allowed) ----------
__device__ __half g_as[(size_t)MROWS * KA];            // activations, single limb
__device__ __half g_wqkv_s[(size_t)QKV_N * KB];        // stacked W^T [bh|bl]
__device__ __half g_wout_s[(size_t)HID * KB];
// Head-major fp16 Q (single limb) and hi/lo K/V: [b*16+h][s][64]
#define HM_ELEMS ((size_t)BATCH * NHEADS * SEQ * HD)
__device__ __half g_qh[HM_ELEMS];
__device__ __half g_kh[HM_ELEMS], g_kl[HM_ELEMS];
__device__ __half g_vh[HM_ELEMS], g_vl[HM_ELEMS];

// ---------------- PTX helpers (base ISA only) ----------------
__device__ __forceinline__ uint32_t smem_u32(const void* p) {
    uint32_t a;
    asm("{ .reg .u64 t; cvta.to.shared.u64 t, %1; cvt.u32.u64 %0, t; }" : "=r"(a) : "l"(p));
    return a;
}

__device__ __forceinline__ void cp_async16(uint32_t s, const void* g) {
    asm volatile("cp.async.cg.shared.global [%0], [%1], 16;" :: "r"(s), "l"(g) : "memory");
}
#define CP_COMMIT() asm volatile("cp.async.commit_group;" ::: "memory")
#define CP_WAIT1()  asm volatile("cp.async.wait_group 1;"  ::: "memory")

#define LDSM_X4(R0, R1, R2, R3, ADDR)                                          \
    asm volatile("ldmatrix.sync.aligned.m8n8.x4.shared.b16 {%0,%1,%2,%3}, [%4];" \
                 : "=r"(R0), "=r"(R1), "=r"(R2), "=r"(R3) : "r"(ADDR))

#define LDSM_X4T(R0, R1, R2, R3, ADDR)                                         \
    asm volatile("ldmatrix.sync.aligned.m8n8.x4.trans.shared.b16 {%0,%1,%2,%3}, [%4];" \
                 : "=r"(R0), "=r"(R1), "=r"(R2), "=r"(R3) : "r"(ADDR))

// fp16 inputs, f32 accumulate (main pass)
#define MMAF32(D, A, B0, B1)                                                   \
    asm volatile("mma.sync.aligned.m16n8k16.row.col.f32.f16.f16.f32 "          \
                 "{%0,%1,%2,%3},{%4,%5,%6,%7},{%8,%9},{%0,%1,%2,%3};"          \
                 : "+f"((D)[0]), "+f"((D)[1]), "+f"((D)[2]), "+f"((D)[3])      \
                 : "r"((A)[0]), "r"((A)[1]), "r"((A)[2]), "r"((A)[3]),         \
                   "r"(B0), "r"(B1))

// fp16 inputs, f16 accumulate (cross pass; values ~2^-11 of main)
#define MMAF16(D, A, B0, B1)                                                   \
    asm volatile("mma.sync.aligned.m16n8k16.row.col.f16.f16.f16.f16 "          \
                 "{%0,%1},{%2,%3,%4,%5},{%6,%7},{%0,%1};"                      \
                 : "+r"((D)[0]), "+r"((D)[1])                                  \
                 : "r"((A)[0]), "r"((A)[1]), "r"((A)[2]), "r"((A)[3]),         \
                   "r"(B0), "r"(B1))

// exp2 via MUFU (1 issue slot; ~2 ulp).
__device__ __forceinline__ float fexp2(float x) {
    float y;
    asm("ex2.approx.f32 %0, %1;" : "=f"(y) : "f"(x));
    return y;
}

// pack two fp32 -> half2 in ONE instruction (lo in low half), rn rounding
__device__ __forceinline__ uint32_t cvt2h(float lo, float hi) {
    uint32_t r;
    asm("cvt.rn.f16x2.f32 %0, %1, %2;" : "=r"(r) : "f"(hi), "f"(lo));
    return r;
}

#define HMUL2(D, A, B) \
    asm("mul.rn.f16x2 %0, %1, %2;" : "=r"(D) : "r"(A), "r"(B))

__device__ __forceinline__ uint32_t pack2h(__half a, __half b) {
    __half2 t;
    t.x = a; t.y = b;
    return *reinterpret_cast<uint32_t*>(&t);
}

// ---------------------------------------------------------------------------
// Conversion: fp32 activations [R,1024] -> fp16 [R,1024] (single limb)
// ---------------------------------------------------------------------------
__global__ __launch_bounds__(256) void convert_act_kernel(
    const float* __restrict__ in, __half* __restrict__ out, int R)
{
    int idx = blockIdx.x * 256 + threadIdx.x;     // over R*256 float4s
    if (idx >= R * 256) return;
    const float4 v = ((const float4*)in)[idx];
    uint2 h;
    h.x = cvt2h(v.x, v.y);
    h.y = cvt2h(v.z, v.w);
    ((uint2*)out)[idx] = h;
}

// ---------------------------------------------------------------------------
// Conversion + transpose: W fp32 [K=1024, N] -> stacked fp16 [N,2048]=[bh|bl]
// ---------------------------------------------------------------------------
__global__ __launch_bounds__(1024) void convert_w_kernel(
    const float* __restrict__ w, __half* __restrict__ out, int N)
{
    __shared__ float tile[32][33];
    int tx = threadIdx.x & 31;
    int ty = threadIdx.x >> 5;
    int gn = blockIdx.x * 32;
    int gk = blockIdx.y * 32;
    tile[ty][tx] = w[(size_t)(gk + ty) * N + gn + tx];
    __syncthreads();
    float v = tile[tx][ty];
    __half h = __float2half(v);
    __half l = __float2half(v - __half2float(h));
    size_t o = (size_t)(gn + ty) * KB + gk + tx;
    out[o]        = h;
    out[o + 1024] = l;
}

// ---------------------------------------------------------------------------
// HMMA GEMM: C[4096,N] = A[4096,1024] @ (Bh+Bl)[N,1024]^T + bias.
// CTA tile 128x64, 256 threads (8 warps, 4x2), warp tile 32x32.
// 16 K-iterations; per iter: A loaded once, Bh (f32-acc) + Bl (f16-acc).
// mode 0: fp32 C out.  mode 1: QKV epilogue -> fp16 Q (single) / K,V hi-lo.
// ---------------------------------------------------------------------------
#define BM 128
#define BN 64
#define BK 64
#define NKITER (KA / BK)                   // 16
#define A_BYTES (BM * 128)                 // 16 KB
#define B_BYTES (BN * 128)                 // 8 KB
#define STAGE_BYTES (A_BYTES + 2 * B_BYTES)// 32 KB (A, Bh, Bl)
#define GEMM_SMEM (3 * STAGE_BYTES + 128)

__global__ __launch_bounds__(256, 2) void mma_gemm_kernel(
    const __half* __restrict__ As, const __half* __restrict__ Bs,
    const float* __restrict__ bias, float* __restrict__ C, int N, int mode,
    __half* __restrict__ qh,
    __half* __restrict__ kh, __half* __restrict__ kl,
    __half* __restrict__ vh, __half* __restrict__ vl)
{
    extern __shared__ char dsmem[];
    const uint32_t smem_base = (smem_u32(dsmem) + 127u) & ~127u;

    const int tid  = threadIdx.x;
    const int wid  = tid >> 5;
    const int lane = tid & 31;
    const int wm   = wid >> 1;     // 0..3 (32-row slab)
    const int wn   = wid & 1;      // 0..1 (32-col slab)

    const int block_row = blockIdx.y * BM;
    const int block_col = blockIdx.x * BN;

    const __half* Abase = As + (size_t)block_row * KA;
    const __half* Bbase = Bs + (size_t)block_col * KB;

    auto load_stage = [&](int stage, int kc) {
        const uint32_t sA  = smem_base + stage * STAGE_BYTES;
        const uint32_t sBh = sA + A_BYTES;
        const uint32_t sBl = sBh + B_BYTES;
#pragma unroll
        for (int i = 0; i < 4; i++) {       // A: 1024 16B segs
            const int s   = i * 256 + tid;
            const int row = s >> 3;
            const int ch  = s & 7;
            const uint32_t sw = (uint32_t)(ch * 16) ^ (uint32_t)((row & 7) << 4);
            cp_async16(sA + row * 128 + sw, Abase + (size_t)row * KA + kc + ch * 8);
        }
#pragma unroll
        for (int i = 0; i < 2; i++) {       // Bh + Bl: 512 segs each
            const int s   = i * 256 + tid;
            const int row = s >> 3;
            const int ch  = s & 7;
            const uint32_t sw = (uint32_t)(ch * 16) ^ (uint32_t)((row & 7) << 4);
            const __half* bp = Bbase + (size_t)row * KB + kc + ch * 8;
            cp_async16(sBh + row * 128 + sw, bp);
            cp_async16(sBl + row * 128 + sw, bp + 1024);
        }
        CP_COMMIT();
    };

    float    facc[2][4][4];
    uint32_t hacc[2][4][2];
#pragma unroll
    for (int mt = 0; mt < 2; mt++)
#pragma unroll
        for (int nt = 0; nt < 4; nt++) {
#pragma unroll
            for (int r = 0; r < 4; r++) facc[mt][nt][r] = 0.0f;
            hacc[mt][nt][0] = 0u; hacc[mt][nt][1] = 0u;
        }

    load_stage(0, 0);
    load_stage(1, BK);

    const int lrow  = lane & 15;
    const int kseg  = (lane >> 4) * 16;
    const uint32_t arow_off = (uint32_t)(wm * 32 + lrow) * 128;
    const uint32_t brow_off = (uint32_t)(wn * 32 + lrow) * 128;
    const uint32_t aswz = (uint32_t)((lrow & 7) << 4);

    for (int it = 0; it < NKITER; it++) {
        CP_WAIT1();
        __syncthreads();
        if (it + 2 < NKITER) load_stage((it + 2) % 3, (it + 2) * BK);
        else                 CP_COMMIT();
        const uint32_t sA  = smem_base + (it % 3) * STAGE_BYTES;
        const uint32_t sBh = sA + A_BYTES;
        const uint32_t sBl = sBh + B_BYTES;
#pragma unroll
        for (int kt = 0; kt < 4; kt++) {
            const uint32_t koff = ((uint32_t)(kt * 32 + kseg)) ^ aswz;
            uint32_t a[2][4], bh_[2][4], bl_[2][4];
#pragma unroll
            for (int mt = 0; mt < 2; mt++)
                LDSM_X4(a[mt][0], a[mt][1], a[mt][2], a[mt][3],
                        sA + arow_off + (uint32_t)(mt * 16 * 128) + koff);
#pragma unroll
            for (int pr = 0; pr < 2; pr++) {
                const uint32_t bo = brow_off + (uint32_t)(pr * 16 * 128) + koff;
                LDSM_X4(bh_[pr][0], bh_[pr][1], bh_[pr][2], bh_[pr][3], sBh + bo);
                LDSM_X4(bl_[pr][0], bl_[pr][1], bl_[pr][2], bl_[pr][3], sBl + bo);
            }
#pragma unroll
            for (int mt = 0; mt < 2; mt++)
#pragma unroll
                for (int nt = 0; nt < 4; nt++) {
                    const int pr = nt >> 1, sub = nt & 1;
                    MMAF32(facc[mt][nt], a[mt], bh_[pr][sub], bh_[pr][sub + 2]);
                    MMAF16(hacc[mt][nt], a[mt], bl_[pr][sub], bl_[pr][sub + 2]);
                }
        }
        __syncthreads();
    }

    const int rbase = block_row + wm * 32 + (lane >> 2);
    const int cbase = block_col + wn * 32 + (lane & 3) * 2;

#pragma unroll
    for (int mt = 0; mt < 2; mt++) {
#pragma unroll
        for (int nt = 0; nt < 4; nt++) {
            const float2 cx01 = __half22float2(*reinterpret_cast<__half2*>(&hacc[mt][nt][0]));
            const float2 cx23 = __half22float2(*reinterpret_cast<__half2*>(&hacc[mt][nt][1]));
            const int col = cbase + nt * 8;
            const float bx = bias[col];
            const float by = bias[col + 1];
            const float r00 = facc[mt][nt][0] + cx01.x + bx;
            const float r01 = facc[mt][nt][1] + cx01.y + by;
            const float r10 = facc[mt][nt][2] + cx23.x + bx;
            const float r11 = facc[mt][nt][3] + cx23.y + by;
            if (mode == 0) {
                const int r0 = rbase + mt * 16;
                float2 o0 = { r00, r01 };
                float2 o1 = { r10, r11 };
                *(float2*)(C + (size_t)r0 * N + col)       = o0;
                *(float2*)(C + (size_t)(r0 + 8) * N + col) = o1;
            } else {
                const int part = col >> 10;          // CTA-uniform (BN=64, head-aligned)
                const int hh   = (col >> 6) & 15;
                const int dd   = col & 63;
#pragma unroll
                for (int rr = 0; rr < 2; rr++) {
                    const int r = rbase + mt * 16 + rr * 8;
                    float v0 = rr ? r10 : r00;
                    float v1 = rr ? r11 : r01;
                    const size_t off =
                        (((size_t)((r >> 11) * 16 + hh)) * SEQ + (r & 2047)) * 64 + dd;
                    if (part == 0) {
                        *(uint32_t*)(qh + off) = cvt2h(v0 * QSCALE, v1 * QSCALE);
                    } else {
                        __half* dh = part == 1 ? kh : vh;
                        __half* dl = part == 1 ? kl : vl;
                        const __half h0 = __float2half(v0);
                        const __half h1 = __float2half(v1);
                        *(uint32_t*)(dh + off) = pack2h(h0, h1);
                        *(uint32_t*)(dl + off) =
                            pack2h(__float2half(v0 - __half2float(h0)),
                                   __float2half(v1 - __half2float(h1)));
                    }
                }
            }
        }
    }
}

// ---------------------------------------------------------------------------
// HMMA causal flash attention, fp16-fed, 2-stage cp.async pipeline,
// 2 CTAs/SM. One CTA = 128 queries of one (b,h); 8 warps x 16 rows;
// 64-key tiles. Q/P single limb; K/V split hi/lo; MUFU exp2 softmax.
// Q fragments hoisted out of the tile loop; PV cross term accumulated in
// f16 across tiles (rescaled per tile with mul.f16x2, folded once at end).
// Output: fp16 [R,1024] rows of g_as.
// smem: QH 16K | 2 stages x {KH,KL,VH,VL 8K each} = 80KB (+pad)
// ---------------------------------------------------------------------------
#define KV_STAGE_BYTES 32768
#define ATTN_SMEM (16384 + 2 * KV_STAGE_BYTES + 128)

__global__ __launch_bounds__(256, 2) void attn_mma_kernel(
    const __half* __restrict__ qh_g,
    const __half* __restrict__ kh_g, const __half* __restrict__ kl_g,
    const __half* __restrict__ vh_g, const __half* __restrict__ vl_g,
    __half* __restrict__ outs)
{
    extern __shared__ char sm[];
    const uint32_t base = (smem_u32(sm) + 127u) & ~127u;
    const uint32_t sQH = base;
    const uint32_t kvbase = base + 16384;

    const int tid  = threadIdx.x;
    const int lane = tid & 31;
    const int wid  = tid >> 5;
    const int qb   = 15 - (int)blockIdx.x;     // heavy blocks first
    const int bh   = blockIdx.y;
    const int b    = bh >> 4;
    const int h    = bh & 15;
    const size_t hrow = (size_t)bh * SEQ;

    // ---- Q tile cp.async (joins group 0) ----
#pragma unroll
    for (int i = 0; i < 4; i++) {
        const int s   = i * 256 + tid;
        const int row = s >> 3;
        const int ch  = s & 7;
        const uint32_t sw = (uint32_t)(ch * 16) ^ (uint32_t)((row & 7) << 4);
        const size_t gofs = (hrow + qb * 128 + row) * 64 + ch * 8;
        cp_async16(sQH + row * 128 + sw, qh_g + gofs);
    }

    auto load_kv = [&](int stage, int k0) {
        const uint32_t sb = kvbase + stage * KV_STAGE_BYTES;
#pragma unroll
        for (int i = 0; i < 2; i++) {
            const int s   = i * 256 + tid;
            const int row = s >> 3;
            const int ch  = s & 7;
            const uint32_t sw = (uint32_t)(ch * 16) ^ (uint32_t)((row & 7) << 4);
            const uint32_t so = row * 128 + sw;
            const size_t gofs = (hrow + k0 + row) * 64 + ch * 8;
            cp_async16(sb + so,         kh_g + gofs);
            cp_async16(sb + 8192 + so,  kl_g + gofs);
            cp_async16(sb + 16384 + so, vh_g + gofs);
            cp_async16(sb + 24576 + so, vl_g + gofs);
        }
        CP_COMMIT();
    };

    const int nk = (qb + 1) * 2;
    load_kv(0, 0);                 // group 0 (with Q)

    float acc_o[8][4];
    uint32_t ocx[8][2];            // persistent f16 cross accumulator (PV)
#pragma unroll
    for (int nt = 0; nt < 8; nt++) {
#pragma unroll
        for (int r = 0; r < 4; r++) acc_o[nt][r] = 0.0f;
        ocx[nt][0] = 0u; ocx[nt][1] = 0u;
    }
    float m0 = -1e30f, m1 = -1e30f, l0 = 0.0f, l1 = 0.0f;

    const int r0      = lane >> 2;
    const int qrow_w  = qb * 128 + wid * 16;
    const int qg0     = qrow_w + r0;

    const int a_r = wid * 16 + (lane & 15);
    const int a_c = (lane >> 4) * 16;
    const uint32_t a_row_off = (uint32_t)(a_r * 128);
    const uint32_t a_sw = (uint32_t)((a_r & 7) << 4);
    const int g      = lane >> 3;
    const int br_off = lane & 7;

    uint32_t qf[4][4];             // Q fragments, loaded once (tile-invariant)

    for (int t = 0; t < nk; t++) {
        const int k0 = t * 64;
        if (t + 1 < nk) load_kv((t + 1) & 1, (t + 1) * 64);
        else            CP_COMMIT();
        CP_WAIT1();                // stage t's group complete
        __syncthreads();

        if (t == 0) {              // hoisted Q fragment load (Q never changes)
#pragma unroll
            for (int kc = 0; kc < 4; kc++) {
                const uint32_t qoff = ((uint32_t)(kc * 32 + a_c)) ^ a_sw;
                LDSM_X4(qf[kc][0], qf[kc][1], qf[kc][2], qf[kc][3],
                        sQH + a_row_off + qoff);
            }
        }

        const uint32_t st  = kvbase + (t & 1) * KV_STAGE_BYTES;
        const uint32_t sKH = st;
        const uint32_t sKL = st + 8192;
        const uint32_t sVH = st + 16384;
        const uint32_t sVL = st + 24576;

        // ---- S = Q K^T: main (q*kh) f32, cross (q*kl) f16 ----
        float s[8][4];
        uint32_t scx[8][2];
#pragma unroll
        for (int nt = 0; nt < 8; nt++) {
#pragma unroll
            for (int r = 0; r < 4; r++) s[nt][r] = 0.0f;
            scx[nt][0] = 0u; scx[nt][1] = 0u;
        }

#pragma unroll
        for (int kc = 0; kc < 4; kc++) {
#pragma unroll
            for (int np = 0; np < 4; np++) {
                const int brow = np * 16 + ((g & 2) << 2) + br_off;
                const uint32_t boff = ((uint32_t)(kc * 32 + ((g & 1) << 4)))
                                    ^ (uint32_t)((brow & 7) << 4);
                const uint32_t rb = (uint32_t)(brow * 128) + boff;
                uint32_t kh0, kh1, kh2, kh3, kl0, kl1, kl2, kl3;
                LDSM_X4(kh0, kh1, kh2, kh3, sKH + rb);
                LDSM_X4(kl0, kl1, kl2, kl3, sKL + rb);
                MMAF32(s[2 * np],     qf[kc], kh0, kh1);
                MMAF32(s[2 * np + 1], qf[kc], kh2, kh3);
                MMAF16(scx[2 * np],     qf[kc], kl0, kl1);
                MMAF16(scx[2 * np + 1], qf[kc], kl2, kl3);
            }
        }
        // fold S cross terms (needed before softmax)
#pragma unroll
        for (int nt = 0; nt < 8; nt++) {
            const float2 cA = __half22float2(*reinterpret_cast<__half2*>(&scx[nt][0]));
            const float2 cB = __half22float2(*reinterpret_cast<__half2*>(&scx[nt][1]));
            s[nt][0] += cA.x; s[nt][1] += cA.y;
            s[nt][2] += cB.x; s[nt][3] += cB.y;
        }

        // ---- causal mask ----
        if (k0 + 63 > qrow_w) {
#pragma unroll
            for (int nt = 0; nt < 8; nt++) {
                const int kg0 = k0 + nt * 8 + 2 * (lane & 3);
                if (kg0     > qg0)     s[nt][0] = -1e30f;
                if (kg0 + 1 > qg0)     s[nt][1] = -1e30f;
                if (kg0     > qg0 + 8) s[nt][2] = -1e30f;
                if (kg0 + 1 > qg0 + 8) s[nt][3] = -1e30f;
            }
        }

        // ---- online softmax (base-2, MUFU exp2) ----
        float rx0 = -1e30f, rx1 = -1e30f;
#pragma unroll
        for (int nt = 0; nt < 8; nt++) {
            rx0 = fmaxf(rx0, fmaxf(s[nt][0], s[nt][1]));
            rx1 = fmaxf(rx1, fmaxf(s[nt][2], s[nt][3]));
        }
        rx0 = fmaxf(rx0, __shfl_xor_sync(0xffffffffu, rx0, 1));
        rx0 = fmaxf(rx0, __shfl_xor_sync(0xffffffffu, rx0, 2));
        rx1 = fmaxf(rx1, __shfl_xor_sync(0xffffffffu, rx1, 1));
        rx1 = fmaxf(rx1, __shfl_xor_sync(0xffffffffu, rx1, 2));
        const float mn0 = fmaxf(m0, rx0);
        const float mn1 = fmaxf(m1, rx1);
        const float sc0 = fexp2(m0 - mn0);
        const float sc1 = fexp2(m1 - mn1);
        m0 = mn0; m1 = mn1;
        l0 *= sc0; l1 *= sc1;
        const uint32_t sc0h = cvt2h(sc0, sc0);
        const uint32_t sc1h = cvt2h(sc1, sc1);
#pragma unroll
        for (int nt = 0; nt < 8; nt++) {
            acc_o[nt][0] *= sc0; acc_o[nt][1] *= sc0;
            acc_o[nt][2] *= sc1; acc_o[nt][3] *= sc1;
            HMUL2(ocx[nt][0], ocx[nt][0], sc0h);
            HMUL2(ocx[nt][1], ocx[nt][1], sc1h);
        }

        uint32_t ph[4][4];
#pragma unroll
        for (int nt = 0; nt < 8; nt++) {
            const float p0 = fexp2(s[nt][0] - m0);
            const float p1 = fexp2(s[nt][1] - m0);
            const float p2 = fexp2(s[nt][2] - m1);
            const float p3 = fexp2(s[nt][3] - m1);
            l0 += p0 + p1;
            l1 += p2 + p3;
            const int kc = nt >> 1;
            const int rr = (nt & 1) * 2;
            ph[kc][rr]     = cvt2h(p0, p1);
            ph[kc][rr + 1] = cvt2h(p2, p3);
        }

        // ---- O += P V: main (p*vh) f32; cross (p*vl) f16 into ocx ----
#pragma unroll
        for (int kc = 0; kc < 4; kc++) {
#pragma unroll
            for (int np = 0; np < 4; np++) {
                const int vrow = kc * 16 + ((g & 1) << 3) + br_off;
                const uint32_t voff = ((uint32_t)(np * 32 + ((g & 2) << 3)))
                                    ^ (uint32_t)((vrow & 7) << 4);
                const uint32_t rv = (uint32_t)(vrow * 128) + voff;
                uint32_t vh0, vh1, vh2, vh3, vl0, vl1, vl2, vl3;
                LDSM_X4T(vh0, vh1, vh2, vh3, sVH + rv);
                LDSM_X4T(vl0, vl1, vl2, vl3, sVL + rv);
                MMAF32(acc_o[2 * np],     ph[kc], vh0, vh1);
                MMAF32(acc_o[2 * np + 1], ph[kc], vh2, vh3);
                MMAF16(ocx[2 * np],     ph[kc], vl0, vl1);
                MMAF16(ocx[2 * np + 1], ph[kc], vl2, vl3);
            }
        }
        __syncthreads();   // buffer (t&1) free for the load issued at t+1
    }

    // ---- fold deferred PV cross terms, normalize, write fp16 rows ----
#pragma unroll
    for (int nt = 0; nt < 8; nt++) {
        const float2 cA = __half22float2(*reinterpret_cast<__half2*>(&ocx[nt][0]));
        const float2 cB = __half22float2(*reinterpret_cast<__half2*>(&ocx[nt][1]));
        acc_o[nt][0] += cA.x; acc_o[nt][1] += cA.y;
        acc_o[nt][2] += cB.x; acc_o[nt][3] += cB.y;
    }

    l0 += __shfl_xor_sync(0xffffffffu, l0, 1);
    l0 += __shfl_xor_sync(0xffffffffu, l0, 2);
    l1 += __shfl_xor_sync(0xffffffffu, l1, 1);
    l1 += __shfl_xor_sync(0xffffffffu, l1, 2);
    const float inv0 = 1.0f / l0;
    const float inv1 = 1.0f / l1;

    const size_t row0 = (size_t)(b * SEQ + qg0) * KA;
    const size_t row1 = row0 + 8 * KA;
    const int colbase = h * HD + 2 * (lane & 3);
#pragma unroll
    for (int nt = 0; nt < 8; nt++) {
        const int col = colbase + nt * 8;
        *(uint32_t*)(outs + row0 + col) =
            cvt2h(acc_o[nt][0] * inv0, acc_o[nt][1] * inv0);
        *(uint32_t*)(outs + row1 + col) =
            cvt2h(acc_o[nt][2] * inv1, acc_o[nt][3] * inv1);
    }
}

// ---------------------------------------------------------------------------
extern "C" void kernel_launch(void* const* d_in, const int* in_sizes, int n_in,
                              void* d_out, int out_size)
{
    const float* x     = (const float*)d_in[0];
    const float* w_qkv = (const float*)d_in[1];
    const float* b_qkv = (const float*)d_in[2];
    const float* w_out = (const float*)d_in[3];
    const float* b_out = (const float*)d_in[4];
    float* out = (float*)d_out;

    __half *as, *wqkvs, *wouts, *qh, *kh, *kl, *vh, *vl;
    cudaGetSymbolAddress((void**)&as,    g_as);
    cudaGetSymbolAddress((void**)&wqkvs, g_wqkv_s);
    cudaGetSymbolAddress((void**)&wouts, g_wout_s);
    cudaGetSymbolAddress((void**)&qh, g_qh);
    cudaGetSymbolAddress((void**)&kh, g_kh);
    cudaGetSymbolAddress((void**)&kl, g_kl);
    cudaGetSymbolAddress((void**)&vh, g_vh);
    cudaGetSymbolAddress((void**)&vl, g_vl);

    cudaFuncSetAttribute(mma_gemm_kernel,
                         cudaFuncAttributeMaxDynamicSharedMemorySize, GEMM_SMEM);
    cudaFuncSetAttribute(attn_mma_kernel,
                         cudaFuncAttributeMaxDynamicSharedMemorySize, ATTN_SMEM);

    // 1) Convert weights (transpose + fp16 hi/lo split)
    {
        dim3 grid(QKV_N / 32, HID / 32);
        convert_w_kernel<<<grid, 1024>>>(w_qkv, wqkvs, QKV_N);
    }
    {
        dim3 grid(HID / 32, HID / 32);
        convert_w_kernel<<<grid, 1024>>>(w_out, wouts, HID);
    }
    // 2) Convert x (single limb)
    convert_act_kernel<<<(MROWS * 256 + 255) / 256, 256>>>(x, as, MROWS);
    // 3) QKV projection -> head-major fp16 Q / hi-lo K,V (mode 1)
    {
        dim3 grid(QKV_N / BN, MROWS / BM);
        mma_gemm_kernel<<<grid, 256, GEMM_SMEM>>>(as, wqkvs, b_qkv, nullptr,
                                                  QKV_N, 1,
                                                  qh, kh, kl, vh, vl);
    }
    // 4) HMMA flash attention -> fp16 g_as
    {
        dim3 grid(16, BATCH * NHEADS);
        attn_mma_kernel<<<grid, 256, ATTN_SMEM>>>(qh, kh, kl, vh, vl, as);
    }
    // 5) Output projection (mode 0)
    {
        dim3 grid(HID / BN, MROWS / BM);
        mma_gemm_kernel<<<grid, 256, GEMM_SMEM>>>(as, wouts, b_out, out,
                                                  HID, 0,
                                                  nullptr, nullptr, nullptr,
                                                  nullptr, nullptr);
    }
}

// round 13
// speedup vs baseline: 1.4627x; 1.2512x over previous
#include <cuda_runtime.h>
#include <cuda_fp16.h>
#include <cstdint>
#include <math.h>

// Problem constants
#define BATCH   2
#define SEQ     2048
#define HID     1024
#define NHEADS  16
#define HD      64
#define QKV_N   3072
#define MROWS   4096
#define KA      1024          // activations: single fp16 limb
#define KWB     1024          // weights: single fp16 limb (R13: Bl dropped)

#define QSCALE  0.18033688f   // 0.125 * log2(e)

// ---------------- scratch (device globals; no allocations allowed) ----------
__device__ __half g_as[(size_t)MROWS * KA];            // activations fp16
__device__ __half g_wqkv_s[(size_t)QKV_N * KWB];       // W^T fp16
__device__ __half g_wout_s[(size_t)HID * KWB];
// Head-major fp16 Q (single limb) and hi/lo K/V: [b*16+h][s][64]
#define HM_ELEMS ((size_t)BATCH * NHEADS * SEQ * HD)
__device__ __half g_qh[HM_ELEMS];
__device__ __half g_kh[HM_ELEMS], g_kl[HM_ELEMS];
__device__ __half g_vh[HM_ELEMS], g_vl[HM_ELEMS];

// ---------------- PTX helpers (base ISA only) ----------------
__device__ __forceinline__ uint32_t smem_u32(const void* p) {
    uint32_t a;
    asm("{ .reg .u64 t; cvta.to.shared.u64 t, %1; cvt.u32.u64 %0, t; }" : "=r"(a) : "l"(p));
    return a;
}

__device__ __forceinline__ void cp_async16(uint32_t s, const void* g) {
    asm volatile("cp.async.cg.shared.global [%0], [%1], 16;" :: "r"(s), "l"(g) : "memory");
}
#define CP_COMMIT() asm volatile("cp.async.commit_group;" ::: "memory")
#define CP_WAIT1()  asm volatile("cp.async.wait_group 1;"  ::: "memory")

#define LDSM_X4(R0, R1, R2, R3, ADDR)                                          \
    asm volatile("ldmatrix.sync.aligned.m8n8.x4.shared.b16 {%0,%1,%2,%3}, [%4];" \
                 : "=r"(R0), "=r"(R1), "=r"(R2), "=r"(R3) : "r"(ADDR))

#define LDSM_X4T(R0, R1, R2, R3, ADDR)                                         \
    asm volatile("ldmatrix.sync.aligned.m8n8.x4.trans.shared.b16 {%0,%1,%2,%3}, [%4];" \
                 : "=r"(R0), "=r"(R1), "=r"(R2), "=r"(R3) : "r"(ADDR))

// fp16 inputs, f32 accumulate (main pass)
#define MMAF32(D, A, B0, B1)                                                   \
    asm volatile("mma.sync.aligned.m16n8k16.row.col.f32.f16.f16.f32 "          \
                 "{%0,%1,%2,%3},{%4,%5,%6,%7},{%8,%9},{%0,%1,%2,%3};"          \
                 : "+f"((D)[0]), "+f"((D)[1]), "+f"((D)[2]), "+f"((D)[3])      \
                 : "r"((A)[0]), "r"((A)[1]), "r"((A)[2]), "r"((A)[3]),         \
                   "r"(B0), "r"(B1))

// fp16 inputs, f16 accumulate (attention cross pass; values ~2^-11 of main)
#define MMAF16(D, A, B0, B1)                                                   \
    asm volatile("mma.sync.aligned.m16n8k16.row.col.f16.f16.f16.f16 "          \
                 "{%0,%1},{%2,%3,%4,%5},{%6,%7},{%0,%1};"                      \
                 : "+r"((D)[0]), "+r"((D)[1])                                  \
                 : "r"((A)[0]), "r"((A)[1]), "r"((A)[2]), "r"((A)[3]),         \
                   "r"(B0), "r"(B1))

// exp2 via MUFU (1 issue slot; ~2 ulp).
__device__ __forceinline__ float fexp2(float x) {
    float y;
    asm("ex2.approx.f32 %0, %1;" : "=f"(y) : "f"(x));
    return y;
}

// pack two fp32 -> half2 in ONE instruction (lo in low half), rn rounding
__device__ __forceinline__ uint32_t cvt2h(float lo, float hi) {
    uint32_t r;
    asm("cvt.rn.f16x2.f32 %0, %1, %2;" : "=r"(r) : "f"(hi), "f"(lo));
    return r;
}

#define HMUL2(D, A, B) \
    asm("mul.rn.f16x2 %0, %1, %2;" : "=r"(D) : "r"(A), "r"(B))

__device__ __forceinline__ uint32_t pack2h(__half a, __half b) {
    __half2 t;
    t.x = a; t.y = b;
    return *reinterpret_cast<uint32_t*>(&t);
}

// ---------------------------------------------------------------------------
// Conversion: fp32 activations [R,1024] -> fp16 [R,1024]
// ---------------------------------------------------------------------------
__global__ __launch_bounds__(256) void convert_act_kernel(
    const float* __restrict__ in, __half* __restrict__ out, int R)
{
    int idx = blockIdx.x * 256 + threadIdx.x;     // over R*256 float4s
    if (idx >= R * 256) return;
    const float4 v = ((const float4*)in)[idx];
    uint2 h;
    h.x = cvt2h(v.x, v.y);
    h.y = cvt2h(v.z, v.w);
    ((uint2*)out)[idx] = h;
}

// ---------------------------------------------------------------------------
// Conversion + transpose: W fp32 [K=1024, N] -> fp16 [N,1024]
// ---------------------------------------------------------------------------
__global__ __launch_bounds__(1024) void convert_w_kernel(
    const float* __restrict__ w, __half* __restrict__ out, int N)
{
    __shared__ float tile[32][33];
    int tx = threadIdx.x & 31;
    int ty = threadIdx.x >> 5;
    int gn = blockIdx.x * 32;
    int gk = blockIdx.y * 32;
    tile[ty][tx] = w[(size_t)(gk + ty) * N + gn + tx];
    __syncthreads();
    out[(size_t)(gn + ty) * KWB + gk + tx] = __float2half(tile[tx][ty]);
}

// ---------------------------------------------------------------------------
// HMMA GEMM: C[4096,N] = A[4096,1024] @ B[N,1024]^T + bias (fp16 in, f32 acc).
// CTA tile 128x128xBK64, 256 threads (8 warps, 4x2), warp tile 32x64.
// mode 0: fp32 C out.  mode 1: QKV epilogue -> fp16 Q (single) / K,V hi-lo.
// ---------------------------------------------------------------------------
#define BM 128
#define BN 128
#define BK 64
#define NKITER (KA / BK)                   // 16
#define A_BYTES (BM * 128)                 // 16 KB
#define B_BYTES (BN * 128)                 // 16 KB
#define STAGE_BYTES (A_BYTES + B_BYTES)    // 32 KB
#define GEMM_SMEM (3 * STAGE_BYTES + 128)

__global__ __launch_bounds__(256, 2) void mma_gemm_kernel(
    const __half* __restrict__ As, const __half* __restrict__ Bs,
    const float* __restrict__ bias, float* __restrict__ C, int N, int mode,
    __half* __restrict__ qh,
    __half* __restrict__ kh, __half* __restrict__ kl,
    __half* __restrict__ vh, __half* __restrict__ vl)
{
    extern __shared__ char dsmem[];
    const uint32_t smem_base = (smem_u32(dsmem) + 127u) & ~127u;

    const int tid  = threadIdx.x;
    const int wid  = tid >> 5;
    const int lane = tid & 31;
    const int wm   = wid >> 1;     // 0..3 (32-row slab)
    const int wn   = wid & 1;      // 0..1 (64-col slab)

    const int block_row = blockIdx.y * BM;
    const int block_col = blockIdx.x * BN;

    const __half* Abase = As + (size_t)block_row * KA;
    const __half* Bbase = Bs + (size_t)block_col * KWB;

    auto load_stage = [&](int stage, int kc) {
        const uint32_t sA = smem_base + stage * STAGE_BYTES;
        const uint32_t sB = sA + A_BYTES;
#pragma unroll
        for (int i = 0; i < 4; i++) {       // A: 1024 16B segs
            const int s   = i * 256 + tid;
            const int row = s >> 3;
            const int ch  = s & 7;
            const uint32_t sw = (uint32_t)(ch * 16) ^ (uint32_t)((row & 7) << 4);
            cp_async16(sA + row * 128 + sw, Abase + (size_t)row * KA + kc + ch * 8);
        }
#pragma unroll
        for (int i = 0; i < 4; i++) {       // B: 1024 16B segs
            const int s   = i * 256 + tid;
            const int row = s >> 3;
            const int ch  = s & 7;
            const uint32_t sw = (uint32_t)(ch * 16) ^ (uint32_t)((row & 7) << 4);
            cp_async16(sB + row * 128 + sw, Bbase + (size_t)row * KWB + kc + ch * 8);
        }
        CP_COMMIT();
    };

    float facc[2][8][4];
#pragma unroll
    for (int mt = 0; mt < 2; mt++)
#pragma unroll
        for (int nt = 0; nt < 8; nt++)
#pragma unroll
            for (int r = 0; r < 4; r++) facc[mt][nt][r] = 0.0f;

    load_stage(0, 0);
    load_stage(1, BK);

    const int lrow  = lane & 15;
    const int kseg  = (lane >> 4) * 16;
    const uint32_t arow_off = (uint32_t)(wm * 32 + lrow) * 128;
    const uint32_t brow_off = (uint32_t)(wn * 64 + lrow) * 128;
    const uint32_t aswz = (uint32_t)((lrow & 7) << 4);

    for (int it = 0; it < NKITER; it++) {
        CP_WAIT1();
        __syncthreads();
        if (it + 2 < NKITER) load_stage((it + 2) % 3, (it + 2) * BK);
        else                 CP_COMMIT();
        const uint32_t sA = smem_base + (it % 3) * STAGE_BYTES;
        const uint32_t sB = sA + A_BYTES;
#pragma unroll
        for (int kt = 0; kt < 4; kt++) {
            const uint32_t koff = ((uint32_t)(kt * 32 + kseg)) ^ aswz;
            uint32_t a[2][4], bb[4][4];
#pragma unroll
            for (int mt = 0; mt < 2; mt++)
                LDSM_X4(a[mt][0], a[mt][1], a[mt][2], a[mt][3],
                        sA + arow_off + (uint32_t)(mt * 2048) + koff);
#pragma unroll
            for (int pr = 0; pr < 4; pr++)
                LDSM_X4(bb[pr][0], bb[pr][1], bb[pr][2], bb[pr][3],
                        sB + brow_off + (uint32_t)(pr * 2048) + koff);
#pragma unroll
            for (int mt = 0; mt < 2; mt++)
#pragma unroll
                for (int nt = 0; nt < 8; nt++) {
                    const int pr = nt >> 1, sub = nt & 1;
                    MMAF32(facc[mt][nt], a[mt], bb[pr][sub], bb[pr][sub + 2]);
                }
        }
        __syncthreads();
    }

    const int rbase = block_row + wm * 32 + (lane >> 2);
    const int cbase = block_col + wn * 64 + (lane & 3) * 2;

#pragma unroll
    for (int mt = 0; mt < 2; mt++) {
#pragma unroll
        for (int nt = 0; nt < 8; nt++) {
            const int col = cbase + nt * 8;
            const float bx = bias[col];
            const float by = bias[col + 1];
            const float r00 = facc[mt][nt][0] + bx;
            const float r01 = facc[mt][nt][1] + by;
            const float r10 = facc[mt][nt][2] + bx;
            const float r11 = facc[mt][nt][3] + by;
            if (mode == 0) {
                const int r0 = rbase + mt * 16;
                float2 o0 = { r00, r01 };
                float2 o1 = { r10, r11 };
                *(float2*)(C + (size_t)r0 * N + col)       = o0;
                *(float2*)(C + (size_t)(r0 + 8) * N + col) = o1;
            } else {
                const int part = col >> 10;          // warp-uniform (64-col slab, head-aligned)
                const int hh   = (col >> 6) & 15;
                const int dd   = col & 63;
#pragma unroll
                for (int rr = 0; rr < 2; rr++) {
                    const int r = rbase + mt * 16 + rr * 8;
                    float v0 = rr ? r10 : r00;
                    float v1 = rr ? r11 : r01;
                    const size_t off =
                        (((size_t)((r >> 11) * 16 + hh)) * SEQ + (r & 2047)) * 64 + dd;
                    if (part == 0) {
                        *(uint32_t*)(qh + off) = cvt2h(v0 * QSCALE, v1 * QSCALE);
                    } else {
                        __half* dh = part == 1 ? kh : vh;
                        __half* dl = part == 1 ? kl : vl;
                        const __half h0 = __float2half(v0);
                        const __half h1 = __float2half(v1);
                        *(uint32_t*)(dh + off) = pack2h(h0, h1);
                        *(uint32_t*)(dl + off) =
                            pack2h(__float2half(v0 - __half2float(h0)),
                                   __float2half(v1 - __half2float(h1)));
                    }
                }
            }
        }
    }
}

// ---------------------------------------------------------------------------
// HMMA causal flash attention (unchanged from R12): fp16-fed, 2-stage
// cp.async pipeline, 2 CTAs/SM. Q/P single limb; K/V hi-lo; MUFU exp2.
// Q fragments hoisted; PV cross term deferred in persistent f16 acc.
// Output: fp16 [R,1024] rows of g_as.
// ---------------------------------------------------------------------------
#define KV_STAGE_BYTES 32768
#define ATTN_SMEM (16384 + 2 * KV_STAGE_BYTES + 128)

__global__ __launch_bounds__(256, 2) void attn_mma_kernel(
    const __half* __restrict__ qh_g,
    const __half* __restrict__ kh_g, const __half* __restrict__ kl_g,
    const __half* __restrict__ vh_g, const __half* __restrict__ vl_g,
    __half* __restrict__ outs)
{
    extern __shared__ char sm[];
    const uint32_t base = (smem_u32(sm) + 127u) & ~127u;
    const uint32_t sQH = base;
    const uint32_t kvbase = base + 16384;

    const int tid  = threadIdx.x;
    const int lane = tid & 31;
    const int wid  = tid >> 5;
    const int qb   = 15 - (int)blockIdx.x;     // heavy blocks first
    const int bh   = blockIdx.y;
    const int b    = bh >> 4;
    const int h    = bh & 15;
    const size_t hrow = (size_t)bh * SEQ;

    // ---- Q tile cp.async (joins group 0) ----
#pragma unroll
    for (int i = 0; i < 4; i++) {
        const int s   = i * 256 + tid;
        const int row = s >> 3;
        const int ch  = s & 7;
        const uint32_t sw = (uint32_t)(ch * 16) ^ (uint32_t)((row & 7) << 4);
        const size_t gofs = (hrow + qb * 128 + row) * 64 + ch * 8;
        cp_async16(sQH + row * 128 + sw, qh_g + gofs);
    }

    auto load_kv = [&](int stage, int k0) {
        const uint32_t sb = kvbase + stage * KV_STAGE_BYTES;
#pragma unroll
        for (int i = 0; i < 2; i++) {
            const int s   = i * 256 + tid;
            const int row = s >> 3;
            const int ch  = s & 7;
            const uint32_t sw = (uint32_t)(ch * 16) ^ (uint32_t)((row & 7) << 4);
            const uint32_t so = row * 128 + sw;
            const size_t gofs = (hrow + k0 + row) * 64 + ch * 8;
            cp_async16(sb + so,         kh_g + gofs);
            cp_async16(sb + 8192 + so,  kl_g + gofs);
            cp_async16(sb + 16384 + so, vh_g + gofs);
            cp_async16(sb + 24576 + so, vl_g + gofs);
        }
        CP_COMMIT();
    };

    const int nk = (qb + 1) * 2;
    load_kv(0, 0);                 // group 0 (with Q)

    float acc_o[8][4];
    uint32_t ocx[8][2];            // persistent f16 cross accumulator (PV)
#pragma unroll
    for (int nt = 0; nt < 8; nt++) {
#pragma unroll
        for (int r = 0; r < 4; r++) acc_o[nt][r] = 0.0f;
        ocx[nt][0] = 0u; ocx[nt][1] = 0u;
    }
    float m0 = -1e30f, m1 = -1e30f, l0 = 0.0f, l1 = 0.0f;

    const int r0      = lane >> 2;
    const int qrow_w  = qb * 128 + wid * 16;
    const int qg0     = qrow_w + r0;

    const int a_r = wid * 16 + (lane & 15);
    const int a_c = (lane >> 4) * 16;
    const uint32_t a_row_off = (uint32_t)(a_r * 128);
    const uint32_t a_sw = (uint32_t)((a_r & 7) << 4);
    const int g      = lane >> 3;
    const int br_off = lane & 7;

    uint32_t qf[4][4];             // Q fragments, loaded once (tile-invariant)

    for (int t = 0; t < nk; t++) {
        const int k0 = t * 64;
        if (t + 1 < nk) load_kv((t + 1) & 1, (t + 1) * 64);
        else            CP_COMMIT();
        CP_WAIT1();                // stage t's group complete
        __syncthreads();

        if (t == 0) {              // hoisted Q fragment load (Q never changes)
#pragma unroll
            for (int kc = 0; kc < 4; kc++) {
                const uint32_t qoff = ((uint32_t)(kc * 32 + a_c)) ^ a_sw;
                LDSM_X4(qf[kc][0], qf[kc][1], qf[kc][2], qf[kc][3],
                        sQH + a_row_off + qoff);
            }
        }

        const uint32_t st  = kvbase + (t & 1) * KV_STAGE_BYTES;
        const uint32_t sKH = st;
        const uint32_t sKL = st + 8192;
        const uint32_t sVH = st + 16384;
        const uint32_t sVL = st + 24576;

        // ---- S = Q K^T: main (q*kh) f32, cross (q*kl) f16 ----
        float s[8][4];
        uint32_t scx[8][2];
#pragma unroll
        for (int nt = 0; nt < 8; nt++) {
#pragma unroll
            for (int r = 0; r < 4; r++) s[nt][r] = 0.0f;
            scx[nt][0] = 0u; scx[nt][1] = 0u;
        }

#pragma unroll
        for (int kc = 0; kc < 4; kc++) {
#pragma unroll
            for (int np = 0; np < 4; np++) {
                const int brow = np * 16 + ((g & 2) << 2) + br_off;
                const uint32_t boff = ((uint32_t)(kc * 32 + ((g & 1) << 4)))
                                    ^ (uint32_t)((brow & 7) << 4);
                const uint32_t rb = (uint32_t)(brow * 128) + boff;
                uint32_t kh0, kh1, kh2, kh3, kl0, kl1, kl2, kl3;
                LDSM_X4(kh0, kh1, kh2, kh3, sKH + rb);
                LDSM_X4(kl0, kl1, kl2, kl3, sKL + rb);
                MMAF32(s[2 * np],     qf[kc], kh0, kh1);
                MMAF32(s[2 * np + 1], qf[kc], kh2, kh3);
                MMAF16(scx[2 * np],     qf[kc], kl0, kl1);
                MMAF16(scx[2 * np + 1], qf[kc], kl2, kl3);
            }
        }
        // fold S cross terms (needed before softmax)
#pragma unroll
        for (int nt = 0; nt < 8; nt++) {
            const float2 cA = __half22float2(*reinterpret_cast<__half2*>(&scx[nt][0]));
            const float2 cB = __half22float2(*reinterpret_cast<__half2*>(&scx[nt][1]));
            s[nt][0] += cA.x; s[nt][1] += cA.y;
            s[nt][2] += cB.x; s[nt][3] += cB.y;
        }

        // ---- causal mask ----
        if (k0 + 63 > qrow_w) {
#pragma unroll
            for (int nt = 0; nt < 8; nt++) {
                const int kg0 = k0 + nt * 8 + 2 * (lane & 3);
                if (kg0     > qg0)     s[nt][0] = -1e30f;
                if (kg0 + 1 > qg0)     s[nt][1] = -1e30f;
                if (kg0     > qg0 + 8) s[nt][2] = -1e30f;
                if (kg0 + 1 > qg0 + 8) s[nt][3] = -1e30f;
            }
        }

        // ---- online softmax (base-2, MUFU exp2) ----
        float rx0 = -1e30f, rx1 = -1e30f;
#pragma unroll
        for (int nt = 0; nt < 8; nt++) {
            rx0 = fmaxf(rx0, fmaxf(s[nt][0], s[nt][1]));
            rx1 = fmaxf(rx1, fmaxf(s[nt][2], s[nt][3]));
        }
        rx0 = fmaxf(rx0, __shfl_xor_sync(0xffffffffu, rx0, 1));
        rx0 = fmaxf(rx0, __shfl_xor_sync(0xffffffffu, rx0, 2));
        rx1 = fmaxf(rx1, __shfl_xor_sync(0xffffffffu, rx1, 1));
        rx1 = fmaxf(rx1, __shfl_xor_sync(0xffffffffu, rx1, 2));
        const float mn0 = fmaxf(m0, rx0);
        const float mn1 = fmaxf(m1, rx1);
        const float sc0 = fexp2(m0 - mn0);
        const float sc1 = fexp2(m1 - mn1);
        m0 = mn0; m1 = mn1;
        l0 *= sc0; l1 *= sc1;
        const uint32_t sc0h = cvt2h(sc0, sc0);
        const uint32_t sc1h = cvt2h(sc1, sc1);
#pragma unroll
        for (int nt = 0; nt < 8; nt++) {
            acc_o[nt][0] *= sc0; acc_o[nt][1] *= sc0;
            acc_o[nt][2] *= sc1; acc_o[nt][3] *= sc1;
            HMUL2(ocx[nt][0], ocx[nt][0], sc0h);
            HMUL2(ocx[nt][1], ocx[nt][1], sc1h);
        }

        uint32_t ph[4][4];
#pragma unroll
        for (int nt = 0; nt < 8; nt++) {
            const float p0 = fexp2(s[nt][0] - m0);
            const float p1 = fexp2(s[nt][1] - m0);
            const float p2 = fexp2(s[nt][2] - m1);
            const float p3 = fexp2(s[nt][3] - m1);
            l0 += p0 + p1;
            l1 += p2 + p3;
            const int kc = nt >> 1;
            const int rr = (nt & 1) * 2;
            ph[kc][rr]     = cvt2h(p0, p1);
            ph[kc][rr + 1] = cvt2h(p2, p3);
        }

        // ---- O += P V: main (p*vh) f32; cross (p*vl) f16 into ocx ----
#pragma unroll
        for (int kc = 0; kc < 4; kc++) {
#pragma unroll
            for (int np = 0; np < 4; np++) {
                const int vrow = kc * 16 + ((g & 1) << 3) + br_off;
                const uint32_t voff = ((uint32_t)(np * 32 + ((g & 2) << 3)))
                                    ^ (uint32_t)((vrow & 7) << 4);
                const uint32_t rv = (uint32_t)(vrow * 128) + voff;
                uint32_t vh0, vh1, vh2, vh3, vl0, vl1, vl2, vl3;
                LDSM_X4T(vh0, vh1, vh2, vh3, sVH + rv);
                LDSM_X4T(vl0, vl1, vl2, vl3, sVL + rv);
                MMAF32(acc_o[2 * np],     ph[kc], vh0, vh1);
                MMAF32(acc_o[2 * np + 1], ph[kc], vh2, vh3);
                MMAF16(ocx[2 * np],     ph[kc], vl0, vl1);
                MMAF16(ocx[2 * np + 1], ph[kc], vl2, vl3);
            }
        }
        __syncthreads();   // buffer (t&1) free for the load issued at t+1
    }

    // ---- fold deferred PV cross terms, normalize, write fp16 rows ----
#pragma unroll
    for (int nt = 0; nt < 8; nt++) {
        const float2 cA = __half22float2(*reinterpret_cast<__half2*>(&ocx[nt][0]));
        const float2 cB = __half22float2(*reinterpret_cast<__half2*>(&ocx[nt][1]));
        acc_o[nt][0] += cA.x; acc_o[nt][1] += cA.y;
        acc_o[nt][2] += cB.x; acc_o[nt][3] += cB.y;
    }

    l0 += __shfl_xor_sync(0xffffffffu, l0, 1);
    l0 += __shfl_xor_sync(0xffffffffu, l0, 2);
    l1 += __shfl_xor_sync(0xffffffffu, l1, 1);
    l1 += __shfl_xor_sync(0xffffffffu, l1, 2);
    const float inv0 = 1.0f / l0;
    const float inv1 = 1.0f / l1;

    const size_t row0 = (size_t)(b * SEQ + qg0) * KA;
    const size_t row1 = row0 + 8 * KA;
    const int colbase = h * HD + 2 * (lane & 3);
#pragma unroll
    for (int nt = 0; nt < 8; nt++) {
        const int col = colbase + nt * 8;
        *(uint32_t*)(outs + row0 + col) =
            cvt2h(acc_o[nt][0] * inv0, acc_o[nt][1] * inv0);
        *(uint32_t*)(outs + row1 + col) =
            cvt2h(acc_o[nt][2] * inv1, acc_o[nt][3] * inv1);
    }
}

// ---------------------------------------------------------------------------
extern "C" void kernel_launch(void* const* d_in, const int* in_sizes, int n_in,
                              void* d_out, int out_size)
{
    const float* x     = (const float*)d_in[0];
    const float* w_qkv = (const float*)d_in[1];
    const float* b_qkv = (const float*)d_in[2];
    const float* w_out = (const float*)d_in[3];
    const float* b_out = (const float*)d_in[4];
    float* out = (float*)d_out;

    __half *as, *wqkvs, *wouts, *qh, *kh, *kl, *vh, *vl;
    cudaGetSymbolAddress((void**)&as,    g_as);
    cudaGetSymbolAddress((void**)&wqkvs, g_wqkv_s);
    cudaGetSymbolAddress((void**)&wouts, g_wout_s);
    cudaGetSymbolAddress((void**)&qh, g_qh);
    cudaGetSymbolAddress((void**)&kh, g_kh);
    cudaGetSymbolAddress((void**)&kl, g_kl);
    cudaGetSymbolAddress((void**)&vh, g_vh);
    cudaGetSymbolAddress((void**)&vl, g_vl);

    cudaFuncSetAttribute(mma_gemm_kernel,
                         cudaFuncAttributeMaxDynamicSharedMemorySize, GEMM_SMEM);
    cudaFuncSetAttribute(attn_mma_kernel,
                         cudaFuncAttributeMaxDynamicSharedMemorySize, ATTN_SMEM);

    // 1) Convert weights (transpose, single fp16 limb)
    {
        dim3 grid(QKV_N / 32, HID / 32);
        convert_w_kernel<<<grid, 1024>>>(w_qkv, wqkvs, QKV_N);
    }
    {
        dim3 grid(HID / 32, HID / 32);
        convert_w_kernel<<<grid, 1024>>>(w_out, wouts, HID);
    }
    // 2) Convert x
    convert_act_kernel<<<(MROWS * 256 + 255) / 256, 256>>>(x, as, MROWS);
    // 3) QKV projection -> head-major fp16 Q / hi-lo K,V (mode 1)
    {
        dim3 grid(QKV_N / BN, MROWS / BM);
        mma_gemm_kernel<<<grid, 256, GEMM_SMEM>>>(as, wqkvs, b_qkv, nullptr,
                                                  QKV_N, 1,
                                                  qh, kh, kl, vh, vl);
    }
    // 4) HMMA flash attention -> fp16 g_as
    {
        dim3 grid(16, BATCH * NHEADS);
        attn_mma_kernel<<<grid, 256, ATTN_SMEM>>>(qh, kh, kl, vh, vl, as);
    }
    // 5) Output projection (mode 0)
    {
        dim3 grid(HID / BN, MROWS / BM);
        mma_gemm_kernel<<<grid, 256, GEMM_SMEM>>>(as, wouts, b_out, out,
                                                  HID, 0,
                                                  nullptr, nullptr, nullptr,
                                                  nullptr, nullptr);
    }
}

// round 14
// speedup vs baseline: 1.8989x; 1.2982x over previous
#include <cuda_runtime.h>
#include <cuda_fp16.h>
#include <cstdint>
#include <math.h>

// Problem constants
#define BATCH   2
#define SEQ     2048
#define HID     1024
#define NHEADS  16
#define HD      64
#define QKV_N   3072
#define MROWS   4096
#define KA      1024          // activations: single fp16 limb
#define KWB     1024          // weights: single fp16 limb

#define QSCALE  0.18033688f   // 0.125 * log2(e)

// ---------------- scratch (device globals; no allocations allowed) ----------
__device__ __half g_as[(size_t)MROWS * KA];            // activations fp16
__device__ __half g_wqkv_s[(size_t)QKV_N * KWB];       // W^T fp16
__device__ __half g_wout_s[(size_t)HID * KWB];
// Head-major fp16 Q/K/V (single limb): [b*16+h][s][64]
#define HM_ELEMS ((size_t)BATCH * NHEADS * SEQ * HD)
__device__ __half g_qh[HM_ELEMS];
__device__ __half g_kh[HM_ELEMS];
__device__ __half g_vh[HM_ELEMS];

// ---------------- PTX helpers (base ISA only) ----------------
__device__ __forceinline__ uint32_t smem_u32(const void* p) {
    uint32_t a;
    asm("{ .reg .u64 t; cvta.to.shared.u64 t, %1; cvt.u32.u64 %0, t; }" : "=r"(a) : "l"(p));
    return a;
}

__device__ __forceinline__ void cp_async16(uint32_t s, const void* g) {
    asm volatile("cp.async.cg.shared.global [%0], [%1], 16;" :: "r"(s), "l"(g) : "memory");
}
#define CP_COMMIT() asm volatile("cp.async.commit_group;" ::: "memory")
#define CP_WAIT1()  asm volatile("cp.async.wait_group 1;"  ::: "memory")

#define LDSM_X4(R0, R1, R2, R3, ADDR)                                          \
    asm volatile("ldmatrix.sync.aligned.m8n8.x4.shared.b16 {%0,%1,%2,%3}, [%4];" \
                 : "=r"(R0), "=r"(R1), "=r"(R2), "=r"(R3) : "r"(ADDR))

#define LDSM_X4T(R0, R1, R2, R3, ADDR)                                         \
    asm volatile("ldmatrix.sync.aligned.m8n8.x4.trans.shared.b16 {%0,%1,%2,%3}, [%4];" \
                 : "=r"(R0), "=r"(R1), "=r"(R2), "=r"(R3) : "r"(ADDR))

// fp16 inputs, f32 accumulate
#define MMAF32(D, A, B0, B1)                                                   \
    asm volatile("mma.sync.aligned.m16n8k16.row.col.f32.f16.f16.f32 "          \
                 "{%0,%1,%2,%3},{%4,%5,%6,%7},{%8,%9},{%0,%1,%2,%3};"          \
                 : "+f"((D)[0]), "+f"((D)[1]), "+f"((D)[2]), "+f"((D)[3])      \
                 : "r"((A)[0]), "r"((A)[1]), "r"((A)[2]), "r"((A)[3]),         \
                   "r"(B0), "r"(B1))

// exp2 via MUFU (1 issue slot; ~2 ulp).
__device__ __forceinline__ float fexp2(float x) {
    float y;
    asm("ex2.approx.f32 %0, %1;" : "=f"(y) : "f"(x));
    return y;
}

// pack two fp32 -> half2 in ONE instruction (lo in low half), rn rounding
__device__ __forceinline__ uint32_t cvt2h(float lo, float hi) {
    uint32_t r;
    asm("cvt.rn.f16x2.f32 %0, %1, %2;" : "=r"(r) : "f"(hi), "f"(lo));
    return r;
}

// ---------------------------------------------------------------------------
// Conversion: fp32 activations [R,1024] -> fp16 [R,1024]
// ---------------------------------------------------------------------------
__global__ __launch_bounds__(256) void convert_act_kernel(
    const float* __restrict__ in, __half* __restrict__ out, int R)
{
    int idx = blockIdx.x * 256 + threadIdx.x;     // over R*256 float4s
    if (idx >= R * 256) return;
    const float4 v = ((const float4*)in)[idx];
    uint2 h;
    h.x = cvt2h(v.x, v.y);
    h.y = cvt2h(v.z, v.w);
    ((uint2*)out)[idx] = h;
}

// ---------------------------------------------------------------------------
// Conversion + transpose: W fp32 [K=1024, N] -> fp16 [N,1024]
// ---------------------------------------------------------------------------
__global__ __launch_bounds__(1024) void convert_w_kernel(
    const float* __restrict__ w, __half* __restrict__ out, int N)
{
    __shared__ float tile[32][33];
    int tx = threadIdx.x & 31;
    int ty = threadIdx.x >> 5;
    int gn = blockIdx.x * 32;
    int gk = blockIdx.y * 32;
    tile[ty][tx] = w[(size_t)(gk + ty) * N + gn + tx];
    __syncthreads();
    out[(size_t)(gn + ty) * KWB + gk + tx] = __float2half(tile[tx][ty]);
}

// ---------------------------------------------------------------------------
// HMMA GEMM: C[4096,N] = A[4096,1024] @ B[N,1024]^T + bias (fp16 in, f32 acc).
// CTA tile 128x128xBK64, 256 threads (8 warps, 4x2), warp tile 32x64.
// mode 0: fp32 C out.  mode 1: QKV epilogue -> fp16 Q(scaled)/K/V head-major.
// ---------------------------------------------------------------------------
#define BM 128
#define BN 128
#define BK 64
#define NKITER (KA / BK)                   // 16
#define A_BYTES (BM * 128)                 // 16 KB
#define B_BYTES (BN * 128)                 // 16 KB
#define STAGE_BYTES (A_BYTES + B_BYTES)    // 32 KB
#define GEMM_SMEM (3 * STAGE_BYTES + 128)

__global__ __launch_bounds__(256, 2) void mma_gemm_kernel(
    const __half* __restrict__ As, const __half* __restrict__ Bs,
    const float* __restrict__ bias, float* __restrict__ C, int N, int mode,
    __half* __restrict__ qh, __half* __restrict__ kh, __half* __restrict__ vh)
{
    extern __shared__ char dsmem[];
    const uint32_t smem_base = (smem_u32(dsmem) + 127u) & ~127u;

    const int tid  = threadIdx.x;
    const int wid  = tid >> 5;
    const int lane = tid & 31;
    const int wm   = wid >> 1;     // 0..3 (32-row slab)
    const int wn   = wid & 1;      // 0..1 (64-col slab)

    const int block_row = blockIdx.y * BM;
    const int block_col = blockIdx.x * BN;

    const __half* Abase = As + (size_t)block_row * KA;
    const __half* Bbase = Bs + (size_t)block_col * KWB;

    auto load_stage = [&](int stage, int kc) {
        const uint32_t sA = smem_base + stage * STAGE_BYTES;
        const uint32_t sB = sA + A_BYTES;
#pragma unroll
        for (int i = 0; i < 4; i++) {       // A: 1024 16B segs
            const int s   = i * 256 + tid;
            const int row = s >> 3;
            const int ch  = s & 7;
            const uint32_t sw = (uint32_t)(ch * 16) ^ (uint32_t)((row & 7) << 4);
            cp_async16(sA + row * 128 + sw, Abase + (size_t)row * KA + kc + ch * 8);
        }
#pragma unroll
        for (int i = 0; i < 4; i++) {       // B: 1024 16B segs
            const int s   = i * 256 + tid;
            const int row = s >> 3;
            const int ch  = s & 7;
            const uint32_t sw = (uint32_t)(ch * 16) ^ (uint32_t)((row & 7) << 4);
            cp_async16(sB + row * 128 + sw, Bbase + (size_t)row * KWB + kc + ch * 8);
        }
        CP_COMMIT();
    };

    float facc[2][8][4];
#pragma unroll
    for (int mt = 0; mt < 2; mt++)
#pragma unroll
        for (int nt = 0; nt < 8; nt++)
#pragma unroll
            for (int r = 0; r < 4; r++) facc[mt][nt][r] = 0.0f;

    load_stage(0, 0);
    load_stage(1, BK);

    const int lrow  = lane & 15;
    const int kseg  = (lane >> 4) * 16;
    const uint32_t arow_off = (uint32_t)(wm * 32 + lrow) * 128;
    const uint32_t brow_off = (uint32_t)(wn * 64 + lrow) * 128;
    const uint32_t aswz = (uint32_t)((lrow & 7) << 4);

    for (int it = 0; it < NKITER; it++) {
        CP_WAIT1();
        __syncthreads();
        if (it + 2 < NKITER) load_stage((it + 2) % 3, (it + 2) * BK);
        else                 CP_COMMIT();
        const uint32_t sA = smem_base + (it % 3) * STAGE_BYTES;
        const uint32_t sB = sA + A_BYTES;
#pragma unroll
        for (int kt = 0; kt < 4; kt++) {
            const uint32_t koff = ((uint32_t)(kt * 32 + kseg)) ^ aswz;
            uint32_t a[2][4], bb[4][4];
#pragma unroll
            for (int mt = 0; mt < 2; mt++)
                LDSM_X4(a[mt][0], a[mt][1], a[mt][2], a[mt][3],
                        sA + arow_off + (uint32_t)(mt * 2048) + koff);
#pragma unroll
            for (int pr = 0; pr < 4; pr++)
                LDSM_X4(bb[pr][0], bb[pr][1], bb[pr][2], bb[pr][3],
                        sB + brow_off + (uint32_t)(pr * 2048) + koff);
#pragma unroll
            for (int mt = 0; mt < 2; mt++)
#pragma unroll
                for (int nt = 0; nt < 8; nt++) {
                    const int pr = nt >> 1, sub = nt & 1;
                    MMAF32(facc[mt][nt], a[mt], bb[pr][sub], bb[pr][sub + 2]);
                }
        }
        __syncthreads();
    }

    const int rbase = block_row + wm * 32 + (lane >> 2);
    const int cbase = block_col + wn * 64 + (lane & 3) * 2;

#pragma unroll
    for (int mt = 0; mt < 2; mt++) {
#pragma unroll
        for (int nt = 0; nt < 8; nt++) {
            const int col = cbase + nt * 8;
            const float bx = bias[col];
            const float by = bias[col + 1];
            const float r00 = facc[mt][nt][0] + bx;
            const float r01 = facc[mt][nt][1] + by;
            const float r10 = facc[mt][nt][2] + bx;
            const float r11 = facc[mt][nt][3] + by;
            if (mode == 0) {
                const int r0 = rbase + mt * 16;
                float2 o0 = { r00, r01 };
                float2 o1 = { r10, r11 };
                *(float2*)(C + (size_t)r0 * N + col)       = o0;
                *(float2*)(C + (size_t)(r0 + 8) * N + col) = o1;
            } else {
                const int part = col >> 10;          // warp-uniform (64-col slab)
                const int hh   = (col >> 6) & 15;
                const int dd   = col & 63;
                __half* dst = part == 0 ? qh : (part == 1 ? kh : vh);
                const float sc = part == 0 ? QSCALE : 1.0f;
#pragma unroll
                for (int rr = 0; rr < 2; rr++) {
                    const int r = rbase + mt * 16 + rr * 8;
                    const float v0 = (rr ? r10 : r00) * sc;
                    const float v1 = (rr ? r11 : r01) * sc;
                    const size_t off =
                        (((size_t)((r >> 11) * 16 + hh)) * SEQ + (r & 2047)) * 64 + dd;
                    *(uint32_t*)(dst + off) = cvt2h(v0, v1);
                }
            }
        }
    }
}

// ---------------------------------------------------------------------------
// HMMA causal flash attention, single-limb fp16 Q/K/V, 2-stage cp.async
// pipeline, 2 CTAs/SM. One CTA = 128 queries of one (b,h); 8 warps x 16
// rows; 64-key tiles. MUFU exp2 softmax; Q fragments hoisted.
// Output: fp16 [R,1024] rows of g_as.
// smem: QH 16K | 2 stages x {KH,VH 8K each} = 48KB (+pad)
// ---------------------------------------------------------------------------
#define KV_STAGE_BYTES 16384
#define ATTN_SMEM (16384 + 2 * KV_STAGE_BYTES + 128)

__global__ __launch_bounds__(256, 2) void attn_mma_kernel(
    const __half* __restrict__ qh_g,
    const __half* __restrict__ kh_g, const __half* __restrict__ vh_g,
    __half* __restrict__ outs)
{
    extern __shared__ char sm[];
    const uint32_t base = (smem_u32(sm) + 127u) & ~127u;
    const uint32_t sQH = base;
    const uint32_t kvbase = base + 16384;

    const int tid  = threadIdx.x;
    const int lane = tid & 31;
    const int wid  = tid >> 5;
    const int qb   = 15 - (int)blockIdx.x;     // heavy blocks first
    const int bh   = blockIdx.y;
    const int b    = bh >> 4;
    const int h    = bh & 15;
    const size_t hrow = (size_t)bh * SEQ;

    // ---- Q tile cp.async (joins group 0) ----
#pragma unroll
    for (int i = 0; i < 4; i++) {
        const int s   = i * 256 + tid;
        const int row = s >> 3;
        const int ch  = s & 7;
        const uint32_t sw = (uint32_t)(ch * 16) ^ (uint32_t)((row & 7) << 4);
        const size_t gofs = (hrow + qb * 128 + row) * 64 + ch * 8;
        cp_async16(sQH + row * 128 + sw, qh_g + gofs);
    }

    auto load_kv = [&](int stage, int k0) {
        const uint32_t sb = kvbase + stage * KV_STAGE_BYTES;
#pragma unroll
        for (int i = 0; i < 2; i++) {
            const int s   = i * 256 + tid;
            const int row = s >> 3;
            const int ch  = s & 7;
            const uint32_t sw = (uint32_t)(ch * 16) ^ (uint32_t)((row & 7) << 4);
            const uint32_t so = row * 128 + sw;
            const size_t gofs = (hrow + k0 + row) * 64 + ch * 8;
            cp_async16(sb + so,        kh_g + gofs);
            cp_async16(sb + 8192 + so, vh_g + gofs);
        }
        CP_COMMIT();
    };

    const int nk = (qb + 1) * 2;
    load_kv(0, 0);                 // group 0 (with Q)

    float acc_o[8][4];
#pragma unroll
    for (int nt = 0; nt < 8; nt++)
#pragma unroll
        for (int r = 0; r < 4; r++) acc_o[nt][r] = 0.0f;
    float m0 = -1e30f, m1 = -1e30f, l0 = 0.0f, l1 = 0.0f;

    const int r0      = lane >> 2;
    const int qrow_w  = qb * 128 + wid * 16;
    const int qg0     = qrow_w + r0;

    const int a_r = wid * 16 + (lane & 15);
    const int a_c = (lane >> 4) * 16;
    const uint32_t a_row_off = (uint32_t)(a_r * 128);
    const uint32_t a_sw = (uint32_t)((a_r & 7) << 4);
    const int g      = lane >> 3;
    const int br_off = lane & 7;

    uint32_t qf[4][4];             // Q fragments, loaded once (tile-invariant)

    for (int t = 0; t < nk; t++) {
        const int k0 = t * 64;
        if (t + 1 < nk) load_kv((t + 1) & 1, (t + 1) * 64);
        else            CP_COMMIT();
        CP_WAIT1();                // stage t's group complete
        __syncthreads();

        if (t == 0) {              // hoisted Q fragment load (Q never changes)
#pragma unroll
            for (int kc = 0; kc < 4; kc++) {
                const uint32_t qoff = ((uint32_t)(kc * 32 + a_c)) ^ a_sw;
                LDSM_X4(qf[kc][0], qf[kc][1], qf[kc][2], qf[kc][3],
                        sQH + a_row_off + qoff);
            }
        }

        const uint32_t st  = kvbase + (t & 1) * KV_STAGE_BYTES;
        const uint32_t sKH = st;
        const uint32_t sVH = st + 8192;

        // ---- S = Q K^T (f32 acc) ----
        float s[8][4];
#pragma unroll
        for (int nt = 0; nt < 8; nt++)
#pragma unroll
            for (int r = 0; r < 4; r++) s[nt][r] = 0.0f;

#pragma unroll
        for (int kc = 0; kc < 4; kc++) {
#pragma unroll
            for (int np = 0; np < 4; np++) {
                const int brow = np * 16 + ((g & 2) << 2) + br_off;
                const uint32_t boff = ((uint32_t)(kc * 32 + ((g & 1) << 4)))
                                    ^ (uint32_t)((brow & 7) << 4);
                const uint32_t rb = (uint32_t)(brow * 128) + boff;
                uint32_t kh0, kh1, kh2, kh3;
                LDSM_X4(kh0, kh1, kh2, kh3, sKH + rb);
                MMAF32(s[2 * np],     qf[kc], kh0, kh1);
                MMAF32(s[2 * np + 1], qf[kc], kh2, kh3);
            }
        }

        // ---- causal mask ----
        if (k0 + 63 > qrow_w) {
#pragma unroll
            for (int nt = 0; nt < 8; nt++) {
                const int kg0 = k0 + nt * 8 + 2 * (lane & 3);
                if (kg0     > qg0)     s[nt][0] = -1e30f;
                if (kg0 + 1 > qg0)     s[nt][1] = -1e30f;
                if (kg0     > qg0 + 8) s[nt][2] = -1e30f;
                if (kg0 + 1 > qg0 + 8) s[nt][3] = -1e30f;
            }
        }

        // ---- online softmax (base-2, MUFU exp2) ----
        float rx0 = -1e30f, rx1 = -1e30f;
#pragma unroll
        for (int nt = 0; nt < 8; nt++) {
            rx0 = fmaxf(rx0, fmaxf(s[nt][0], s[nt][1]));
            rx1 = fmaxf(rx1, fmaxf(s[nt][2], s[nt][3]));
        }
        rx0 = fmaxf(rx0, __shfl_xor_sync(0xffffffffu, rx0, 1));
        rx0 = fmaxf(rx0, __shfl_xor_sync(0xffffffffu, rx0, 2));
        rx1 = fmaxf(rx1, __shfl_xor_sync(0xffffffffu, rx1, 1));
        rx1 = fmaxf(rx1, __shfl_xor_sync(0xffffffffu, rx1, 2));
        const float mn0 = fmaxf(m0, rx0);
        const float mn1 = fmaxf(m1, rx1);
        const float sc0 = fexp2(m0 - mn0);
        const float sc1 = fexp2(m1 - mn1);
        m0 = mn0; m1 = mn1;
        l0 *= sc0; l1 *= sc1;
#pragma unroll
        for (int nt = 0; nt < 8; nt++) {
            acc_o[nt][0] *= sc0; acc_o[nt][1] *= sc0;
            acc_o[nt][2] *= sc1; acc_o[nt][3] *= sc1;
        }

        uint32_t ph[4][4];
#pragma unroll
        for (int nt = 0; nt < 8; nt++) {
            const float p0 = fexp2(s[nt][0] - m0);
            const float p1 = fexp2(s[nt][1] - m0);
            const float p2 = fexp2(s[nt][2] - m1);
            const float p3 = fexp2(s[nt][3] - m1);
            l0 += p0 + p1;
            l1 += p2 + p3;
            const int kc = nt >> 1;
            const int rr = (nt & 1) * 2;
            ph[kc][rr]     = cvt2h(p0, p1);
            ph[kc][rr + 1] = cvt2h(p2, p3);
        }

        // ---- O += P V (f32 acc, ldmatrix.trans for V) ----
#pragma unroll
        for (int kc = 0; kc < 4; kc++) {
#pragma unroll
            for (int np = 0; np < 4; np++) {
                const int vrow = kc * 16 + ((g & 1) << 3) + br_off;
                const uint32_t voff = ((uint32_t)(np * 32 + ((g & 2) << 3)))
                                    ^ (uint32_t)((vrow & 7) << 4);
                const uint32_t rv = (uint32_t)(vrow * 128) + voff;
                uint32_t vh0, vh1, vh2, vh3;
                LDSM_X4T(vh0, vh1, vh2, vh3, sVH + rv);
                MMAF32(acc_o[2 * np],     ph[kc], vh0, vh1);
                MMAF32(acc_o[2 * np + 1], ph[kc], vh2, vh3);
            }
        }
        __syncthreads();   // buffer (t&1) free for the load issued at t+1
    }

    // ---- normalize, write fp16 [R,1024] rows of g_as ----
    l0 += __shfl_xor_sync(0xffffffffu, l0, 1);
    l0 += __shfl_xor_sync(0xffffffffu, l0, 2);
    l1 += __shfl_xor_sync(0xffffffffu, l1, 1);
    l1 += __shfl_xor_sync(0xffffffffu, l1, 2);
    const float inv0 = 1.0f / l0;
    const float inv1 = 1.0f / l1;

    const size_t row0 = (size_t)(b * SEQ + qg0) * KA;
    const size_t row1 = row0 + 8 * KA;
    const int colbase = h * HD + 2 * (lane & 3);
#pragma unroll
    for (int nt = 0; nt < 8; nt++) {
        const int col = colbase + nt * 8;
        *(uint32_t*)(outs + row0 + col) =
            cvt2h(acc_o[nt][0] * inv0, acc_o[nt][1] * inv0);
        *(uint32_t*)(outs + row1 + col) =
            cvt2h(acc_o[nt][2] * inv1, acc_o[nt][3] * inv1);
    }
}

// ---------------------------------------------------------------------------
extern "C" void kernel_launch(void* const* d_in, const int* in_sizes, int n_in,
                              void* d_out, int out_size)
{
    const float* x     = (const float*)d_in[0];
    const float* w_qkv = (const float*)d_in[1];
    const float* b_qkv = (const float*)d_in[2];
    const float* w_out = (const float*)d_in[3];
    const float* b_out = (const float*)d_in[4];
    float* out = (float*)d_out;

    __half *as, *wqkvs, *wouts, *qh, *kh, *vh;
    cudaGetSymbolAddress((void**)&as,    g_as);
    cudaGetSymbolAddress((void**)&wqkvs, g_wqkv_s);
    cudaGetSymbolAddress((void**)&wouts, g_wout_s);
    cudaGetSymbolAddress((void**)&qh, g_qh);
    cudaGetSymbolAddress((void**)&kh, g_kh);
    cudaGetSymbolAddress((void**)&vh, g_vh);

    cudaFuncSetAttribute(mma_gemm_kernel,
                         cudaFuncAttributeMaxDynamicSharedMemorySize, GEMM_SMEM);
    cudaFuncSetAttribute(attn_mma_kernel,
                         cudaFuncAttributeMaxDynamicSharedMemorySize, ATTN_SMEM);

    // 1) Convert weights (transpose, fp16)
    {
        dim3 grid(QKV_N / 32, HID / 32);
        convert_w_kernel<<<grid, 1024>>>(w_qkv, wqkvs, QKV_N);
    }
    {
        dim3 grid(HID / 32, HID / 32);
        convert_w_kernel<<<grid, 1024>>>(w_out, wouts, HID);
    }
    // 2) Convert x
    convert_act_kernel<<<(MROWS * 256 + 255) / 256, 256>>>(x, as, MROWS);
    // 3) QKV projection -> head-major fp16 Q/K/V (mode 1)
    {
        dim3 grid(QKV_N / BN, MROWS / BM);
        mma_gemm_kernel<<<grid, 256, GEMM_SMEM>>>(as, wqkvs, b_qkv, nullptr,
                                                  QKV_N, 1, qh, kh, vh);
    }
    // 4) HMMA flash attention -> fp16 g_as
    {
        dim3 grid(16, BATCH * NHEADS);
        attn_mma_kernel<<<grid, 256, ATTN_SMEM>>>(qh, kh, vh, as);
    }
    // 5) Output projection (mode 0)
    {
        dim3 grid(HID / BN, MROWS / BM);
        mma_gemm_kernel<<<grid, 256, GEMM_SMEM>>>(as, wouts, b_out, out,
                                                  HID, 0, nullptr, nullptr, nullptr);
    }
}

// round 15
// speedup vs baseline: 1.9357x; 1.0194x over previous
#include <cuda_runtime.h>
#include <cuda_fp16.h>
#include <cstdint>
#include <math.h>

// Problem constants
#define BATCH   2
#define SEQ     2048
#define HID     1024
#define NHEADS  16
#define HD      64
#define QKV_N   3072
#define MROWS   4096
#define KA      1024          // activations: single fp16 limb
#define KWB     1024          // weights: single fp16 limb

#define QSCALE  0.18033688f   // 0.125 * log2(e)

// ---------------- scratch (device globals; no allocations allowed) ----------
__device__ __half g_as[(size_t)MROWS * KA];            // activations fp16
__device__ __half g_wqkv_s[(size_t)QKV_N * KWB];       // W^T fp16
__device__ __half g_wout_s[(size_t)HID * KWB];
// Head-major fp16 Q/K/V (single limb): [b*16+h][s][64]
#define HM_ELEMS ((size_t)BATCH * NHEADS * SEQ * HD)
__device__ __half g_qh[HM_ELEMS];
__device__ __half g_kh[HM_ELEMS];
__device__ __half g_vh[HM_ELEMS];

// ---------------- PTX helpers (base ISA only) ----------------
__device__ __forceinline__ uint32_t smem_u32(const void* p) {
    uint32_t a;
    asm("{ .reg .u64 t; cvta.to.shared.u64 t, %1; cvt.u32.u64 %0, t; }" : "=r"(a) : "l"(p));
    return a;
}

__device__ __forceinline__ void cp_async16(uint32_t s, const void* g) {
    asm volatile("cp.async.cg.shared.global [%0], [%1], 16;" :: "r"(s), "l"(g) : "memory");
}
#define CP_COMMIT() asm volatile("cp.async.commit_group;" ::: "memory")
#define CP_WAIT1()  asm volatile("cp.async.wait_group 1;"  ::: "memory")

#define LDSM_X4(R0, R1, R2, R3, ADDR)                                          \
    asm volatile("ldmatrix.sync.aligned.m8n8.x4.shared.b16 {%0,%1,%2,%3}, [%4];" \
                 : "=r"(R0), "=r"(R1), "=r"(R2), "=r"(R3) : "r"(ADDR))

#define LDSM_X4T(R0, R1, R2, R3, ADDR)                                         \
    asm volatile("ldmatrix.sync.aligned.m8n8.x4.trans.shared.b16 {%0,%1,%2,%3}, [%4];" \
                 : "=r"(R0), "=r"(R1), "=r"(R2), "=r"(R3) : "r"(ADDR))

// fp16 inputs, f32 accumulate
#define MMAF32(D, A, B0, B1)                                                   \
    asm volatile("mma.sync.aligned.m16n8k16.row.col.f32.f16.f16.f32 "          \
                 "{%0,%1,%2,%3},{%4,%5,%6,%7},{%8,%9},{%0,%1,%2,%3};"          \
                 : "+f"((D)[0]), "+f"((D)[1]), "+f"((D)[2]), "+f"((D)[3])      \
                 : "r"((A)[0]), "r"((A)[1]), "r"((A)[2]), "r"((A)[3]),         \
                   "r"(B0), "r"(B1))

// exp2 via MUFU (1 issue slot; ~2 ulp).
__device__ __forceinline__ float fexp2(float x) {
    float y;
    asm("ex2.approx.f32 %0, %1;" : "=f"(y) : "f"(x));
    return y;
}

// pack two fp32 -> half2 in ONE instruction (lo in low half), rn rounding
__device__ __forceinline__ uint32_t cvt2h(float lo, float hi) {
    uint32_t r;
    asm("cvt.rn.f16x2.f32 %0, %1, %2;" : "=r"(r) : "f"(hi), "f"(lo));
    return r;
}

// ---------------------------------------------------------------------------
// Conversion: fp32 activations [R,1024] -> fp16 [R,1024]
// ---------------------------------------------------------------------------
__global__ __launch_bounds__(256) void convert_act_kernel(
    const float* __restrict__ in, __half* __restrict__ out, int R)
{
    int idx = blockIdx.x * 256 + threadIdx.x;     // over R*256 float4s
    if (idx >= R * 256) return;
    const float4 v = ((const float4*)in)[idx];
    uint2 h;
    h.x = cvt2h(v.x, v.y);
    h.y = cvt2h(v.z, v.w);
    ((uint2*)out)[idx] = h;
}

// ---------------------------------------------------------------------------
// Conversion + transpose: W fp32 [K=1024, N] -> fp16 [N,1024]
// ---------------------------------------------------------------------------
__global__ __launch_bounds__(1024) void convert_w_kernel(
    const float* __restrict__ w, __half* __restrict__ out, int N)
{
    __shared__ float tile[32][33];
    int tx = threadIdx.x & 31;
    int ty = threadIdx.x >> 5;
    int gn = blockIdx.x * 32;
    int gk = blockIdx.y * 32;
    tile[ty][tx] = w[(size_t)(gk + ty) * N + gn + tx];
    __syncthreads();
    out[(size_t)(gn + ty) * KWB + gk + tx] = __float2half(tile[tx][ty]);
}

// ---------------------------------------------------------------------------
// HMMA GEMM: C[4096,N] = A[4096,1024] @ B[N,1024]^T + bias (fp16 in, f32 acc).
// CTA tile 64x128xBK64, 128 threads (4 warps, 2x2), warp tile 32x64.
// 3 CTAs/SM (72KB smem, ~115 regs). Same 16 MMA : 6 ldsm per-kt stream as
// R14 but finer launch grain: QKV grid 1536 (3.46 waves over 444 slots).
// mode 0: fp32 C out.  mode 1: QKV epilogue -> fp16 Q(scaled)/K/V head-major.
// ---------------------------------------------------------------------------
#define BM 64
#define BN 128
#define BK 64
#define NKITER (KA / BK)                   // 16
#define A_BYTES (BM * 128)                 // 8 KB
#define B_BYTES (BN * 128)                 // 16 KB
#define STAGE_BYTES (A_BYTES + B_BYTES)    // 24 KB
#define GEMM_SMEM (3 * STAGE_BYTES + 128)

__global__ __launch_bounds__(128, 3) void mma_gemm_kernel(
    const __half* __restrict__ As, const __half* __restrict__ Bs,
    const float* __restrict__ bias, float* __restrict__ C, int N, int mode,
    __half* __restrict__ qh, __half* __restrict__ kh, __half* __restrict__ vh)
{
    extern __shared__ char dsmem[];
    const uint32_t smem_base = (smem_u32(dsmem) + 127u) & ~127u;

    const int tid  = threadIdx.x;
    const int wid  = tid >> 5;
    const int lane = tid & 31;
    const int wm   = wid >> 1;     // 0..1 (32-row slab)
    const int wn   = wid & 1;      // 0..1 (64-col slab)

    const int block_row = blockIdx.y * BM;
    const int block_col = blockIdx.x * BN;

    const __half* Abase = As + (size_t)block_row * KA;
    const __half* Bbase = Bs + (size_t)block_col * KWB;

    auto load_stage = [&](int stage, int kc) {
        const uint32_t sA = smem_base + stage * STAGE_BYTES;
        const uint32_t sB = sA + A_BYTES;
#pragma unroll
        for (int i = 0; i < 4; i++) {       // A: 512 16B segs
            const int s   = i * 128 + tid;
            const int row = s >> 3;
            const int ch  = s & 7;
            const uint32_t sw = (uint32_t)(ch * 16) ^ (uint32_t)((row & 7) << 4);
            cp_async16(sA + row * 128 + sw, Abase + (size_t)row * KA + kc + ch * 8);
        }
#pragma unroll
        for (int i = 0; i < 8; i++) {       // B: 1024 16B segs
            const int s   = i * 128 + tid;
            const int row = s >> 3;
            const int ch  = s & 7;
            const uint32_t sw = (uint32_t)(ch * 16) ^ (uint32_t)((row & 7) << 4);
            cp_async16(sB + row * 128 + sw, Bbase + (size_t)row * KWB + kc + ch * 8);
        }
        CP_COMMIT();
    };

    float facc[2][8][4];
#pragma unroll
    for (int mt = 0; mt < 2; mt++)
#pragma unroll
        for (int nt = 0; nt < 8; nt++)
#pragma unroll
            for (int r = 0; r < 4; r++) facc[mt][nt][r] = 0.0f;

    load_stage(0, 0);
    load_stage(1, BK);

    const int lrow  = lane & 15;
    const int kseg  = (lane >> 4) * 16;
    const uint32_t arow_off = (uint32_t)(wm * 32 + lrow) * 128;
    const uint32_t brow_off = (uint32_t)(wn * 64 + lrow) * 128;
    const uint32_t aswz = (uint32_t)((lrow & 7) << 4);

    for (int it = 0; it < NKITER; it++) {
        CP_WAIT1();
        __syncthreads();
        if (it + 2 < NKITER) load_stage((it + 2) % 3, (it + 2) * BK);
        else                 CP_COMMIT();
        const uint32_t sA = smem_base + (it % 3) * STAGE_BYTES;
        const uint32_t sB = sA + A_BYTES;
#pragma unroll
        for (int kt = 0; kt < 4; kt++) {
            const uint32_t koff = ((uint32_t)(kt * 32 + kseg)) ^ aswz;
            uint32_t a[2][4], bb[4][4];
#pragma unroll
            for (int mt = 0; mt < 2; mt++)
                LDSM_X4(a[mt][0], a[mt][1], a[mt][2], a[mt][3],
                        sA + arow_off + (uint32_t)(mt * 2048) + koff);
#pragma unroll
            for (int pr = 0; pr < 4; pr++)
                LDSM_X4(bb[pr][0], bb[pr][1], bb[pr][2], bb[pr][3],
                        sB + brow_off + (uint32_t)(pr * 2048) + koff);
#pragma unroll
            for (int mt = 0; mt < 2; mt++)
#pragma unroll
                for (int nt = 0; nt < 8; nt++) {
                    const int pr = nt >> 1, sub = nt & 1;
                    MMAF32(facc[mt][nt], a[mt], bb[pr][sub], bb[pr][sub + 2]);
                }
        }
        __syncthreads();
    }

    const int rbase = block_row + wm * 32 + (lane >> 2);
    const int cbase = block_col + wn * 64 + (lane & 3) * 2;

#pragma unroll
    for (int mt = 0; mt < 2; mt++) {
#pragma unroll
        for (int nt = 0; nt < 8; nt++) {
            const int col = cbase + nt * 8;
            const float bx = bias[col];
            const float by = bias[col + 1];
            const float r00 = facc[mt][nt][0] + bx;
            const float r01 = facc[mt][nt][1] + by;
            const float r10 = facc[mt][nt][2] + bx;
            const float r11 = facc[mt][nt][3] + by;
            if (mode == 0) {
                const int r0 = rbase + mt * 16;
                float2 o0 = { r00, r01 };
                float2 o1 = { r10, r11 };
                *(float2*)(C + (size_t)r0 * N + col)       = o0;
                *(float2*)(C + (size_t)(r0 + 8) * N + col) = o1;
            } else {
                const int part = col >> 10;          // warp-uniform (64-col slab)
                const int hh   = (col >> 6) & 15;
                const int dd   = col & 63;
                __half* dst = part == 0 ? qh : (part == 1 ? kh : vh);
                const float sc = part == 0 ? QSCALE : 1.0f;
#pragma unroll
                for (int rr = 0; rr < 2; rr++) {
                    const int r = rbase + mt * 16 + rr * 8;
                    const float v0 = (rr ? r10 : r00) * sc;
                    const float v1 = (rr ? r11 : r01) * sc;
                    const size_t off =
                        (((size_t)((r >> 11) * 16 + hh)) * SEQ + (r & 2047)) * 64 + dd;
                    *(uint32_t*)(dst + off) = cvt2h(v0, v1);
                }
            }
        }
    }
}

// ---------------------------------------------------------------------------
// HMMA causal flash attention (unchanged from R14): single-limb fp16 Q/K/V,
// 2-stage cp.async pipeline, 2 CTAs/SM. One CTA = 128 queries of one (b,h);
// 8 warps x 16 rows; 64-key tiles. MUFU exp2 softmax; Q fragments hoisted.
// Output: fp16 [R,1024] rows of g_as.
// ---------------------------------------------------------------------------
#define KV_STAGE_BYTES 16384
#define ATTN_SMEM (16384 + 2 * KV_STAGE_BYTES + 128)

__global__ __launch_bounds__(256, 2) void attn_mma_kernel(
    const __half* __restrict__ qh_g,
    const __half* __restrict__ kh_g, const __half* __restrict__ vh_g,
    __half* __restrict__ outs)
{
    extern __shared__ char sm[];
    const uint32_t base = (smem_u32(sm) + 127u) & ~127u;
    const uint32_t sQH = base;
    const uint32_t kvbase = base + 16384;

    const int tid  = threadIdx.x;
    const int lane = tid & 31;
    const int wid  = tid >> 5;
    const int qb   = 15 - (int)blockIdx.x;     // heavy blocks first
    const int bh   = blockIdx.y;
    const int b    = bh >> 4;
    const int h    = bh & 15;
    const size_t hrow = (size_t)bh * SEQ;

    // ---- Q tile cp.async (joins group 0) ----
#pragma unroll
    for (int i = 0; i < 4; i++) {
        const int s   = i * 256 + tid;
        const int row = s >> 3;
        const int ch  = s & 7;
        const uint32_t sw = (uint32_t)(ch * 16) ^ (uint32_t)((row & 7) << 4);
        const size_t gofs = (hrow + qb * 128 + row) * 64 + ch * 8;
        cp_async16(sQH + row * 128 + sw, qh_g + gofs);
    }

    auto load_kv = [&](int stage, int k0) {
        const uint32_t sb = kvbase + stage * KV_STAGE_BYTES;
#pragma unroll
        for (int i = 0; i < 2; i++) {
            const int s   = i * 256 + tid;
            const int row = s >> 3;
            const int ch  = s & 7;
            const uint32_t sw = (uint32_t)(ch * 16) ^ (uint32_t)((row & 7) << 4);
            const uint32_t so = row * 128 + sw;
            const size_t gofs = (hrow + k0 + row) * 64 + ch * 8;
            cp_async16(sb + so,        kh_g + gofs);
            cp_async16(sb + 8192 + so, vh_g + gofs);
        }
        CP_COMMIT();
    };

    const int nk = (qb + 1) * 2;
    load_kv(0, 0);                 // group 0 (with Q)

    float acc_o[8][4];
#pragma unroll
    for (int nt = 0; nt < 8; nt++)
#pragma unroll
        for (int r = 0; r < 4; r++) acc_o[nt][r] = 0.0f;
    float m0 = -1e30f, m1 = -1e30f, l0 = 0.0f, l1 = 0.0f;

    const int r0      = lane >> 2;
    const int qrow_w  = qb * 128 + wid * 16;
    const int qg0     = qrow_w + r0;

    const int a_r = wid * 16 + (lane & 15);
    const int a_c = (lane >> 4) * 16;
    const uint32_t a_row_off = (uint32_t)(a_r * 128);
    const uint32_t a_sw = (uint32_t)((a_r & 7) << 4);
    const int g      = lane >> 3;
    const int br_off = lane & 7;

    uint32_t qf[4][4];             // Q fragments, loaded once (tile-invariant)

    for (int t = 0; t < nk; t++) {
        const int k0 = t * 64;
        if (t + 1 < nk) load_kv((t + 1) & 1, (t + 1) * 64);
        else            CP_COMMIT();
        CP_WAIT1();                // stage t's group complete
        __syncthreads();

        if (t == 0) {              // hoisted Q fragment load (Q never changes)
#pragma unroll
            for (int kc = 0; kc < 4; kc++) {
                const uint32_t qoff = ((uint32_t)(kc * 32 + a_c)) ^ a_sw;
                LDSM_X4(qf[kc][0], qf[kc][1], qf[kc][2], qf[kc][3],
                        sQH + a_row_off + qoff);
            }
        }

        const uint32_t st  = kvbase + (t & 1) * KV_STAGE_BYTES;
        const uint32_t sKH = st;
        const uint32_t sVH = st + 8192;

        // ---- S = Q K^T (f32 acc) ----
        float s[8][4];
#pragma unroll
        for (int nt = 0; nt < 8; nt++)
#pragma unroll
            for (int r = 0; r < 4; r++) s[nt][r] = 0.0f;

#pragma unroll
        for (int kc = 0; kc < 4; kc++) {
#pragma unroll
            for (int np = 0; np < 4; np++) {
                const int brow = np * 16 + ((g & 2) << 2) + br_off;
                const uint32_t boff = ((uint32_t)(kc * 32 + ((g & 1) << 4)))
                                    ^ (uint32_t)((brow & 7) << 4);
                const uint32_t rb = (uint32_t)(brow * 128) + boff;
                uint32_t kh0, kh1, kh2, kh3;
                LDSM_X4(kh0, kh1, kh2, kh3, sKH + rb);
                MMAF32(s[2 * np],     qf[kc], kh0, kh1);
                MMAF32(s[2 * np + 1], qf[kc], kh2, kh3);
            }
        }

        // ---- causal mask ----
        if (k0 + 63 > qrow_w) {
#pragma unroll
            for (int nt = 0; nt < 8; nt++) {
                const int kg0 = k0 + nt * 8 + 2 * (lane & 3);
                if (kg0     > qg0)     s[nt][0] = -1e30f;
                if (kg0 + 1 > qg0)     s[nt][1] = -1e30f;
                if (kg0     > qg0 + 8) s[nt][2] = -1e30f;
                if (kg0 + 1 > qg0 + 8) s[nt][3] = -1e30f;
            }
        }

        // ---- online softmax (base-2, MUFU exp2) ----
        float rx0 = -1e30f, rx1 = -1e30f;
#pragma unroll
        for (int nt = 0; nt < 8; nt++) {
            rx0 = fmaxf(rx0, fmaxf(s[nt][0], s[nt][1]));
            rx1 = fmaxf(rx1, fmaxf(s[nt][2], s[nt][3]));
        }
        rx0 = fmaxf(rx0, __shfl_xor_sync(0xffffffffu, rx0, 1));
        rx0 = fmaxf(rx0, __shfl_xor_sync(0xffffffffu, rx0, 2));
        rx1 = fmaxf(rx1, __shfl_xor_sync(0xffffffffu, rx1, 1));
        rx1 = fmaxf(rx1, __shfl_xor_sync(0xffffffffu, rx1, 2));
        const float mn0 = fmaxf(m0, rx0);
        const float mn1 = fmaxf(m1, rx1);
        const float sc0 = fexp2(m0 - mn0);
        const float sc1 = fexp2(m1 - mn1);
        m0 = mn0; m1 = mn1;
        l0 *= sc0; l1 *= sc1;
#pragma unroll
        for (int nt = 0; nt < 8; nt++) {
            acc_o[nt][0] *= sc0; acc_o[nt][1] *= sc0;
            acc_o[nt][2] *= sc1; acc_o[nt][3] *= sc1;
        }

        uint32_t ph[4][4];
#pragma unroll
        for (int nt = 0; nt < 8; nt++) {
            const float p0 = fexp2(s[nt][0] - m0);
            const float p1 = fexp2(s[nt][1] - m0);
            const float p2 = fexp2(s[nt][2] - m1);
            const float p3 = fexp2(s[nt][3] - m1);
            l0 += p0 + p1;
            l1 += p2 + p3;
            const int kc = nt >> 1;
            const int rr = (nt & 1) * 2;
            ph[kc][rr]     = cvt2h(p0, p1);
            ph[kc][rr + 1] = cvt2h(p2, p3);
        }

        // ---- O += P V (f32 acc, ldmatrix.trans for V) ----
#pragma unroll
        for (int kc = 0; kc < 4; kc++) {
#pragma unroll
            for (int np = 0; np < 4; np++) {
                const int vrow = kc * 16 + ((g & 1) << 3) + br_off;
                const uint32_t voff = ((uint32_t)(np * 32 + ((g & 2) << 3)))
                                    ^ (uint32_t)((vrow & 7) << 4);
                const uint32_t rv = (uint32_t)(vrow * 128) + voff;
                uint32_t vh0, vh1, vh2, vh3;
                LDSM_X4T(vh0, vh1, vh2, vh3, sVH + rv);
                MMAF32(acc_o[2 * np],     ph[kc], vh0, vh1);
                MMAF32(acc_o[2 * np + 1], ph[kc], vh2, vh3);
            }
        }
        __syncthreads();   // buffer (t&1) free for the load issued at t+1
    }

    // ---- normalize, write fp16 [R,1024] rows of g_as ----
    l0 += __shfl_xor_sync(0xffffffffu, l0, 1);
    l0 += __shfl_xor_sync(0xffffffffu, l0, 2);
    l1 += __shfl_xor_sync(0xffffffffu, l1, 1);
    l1 += __shfl_xor_sync(0xffffffffu, l1, 2);
    const float inv0 = 1.0f / l0;
    const float inv1 = 1.0f / l1;

    const size_t row0 = (size_t)(b * SEQ + qg0) * KA;
    const size_t row1 = row0 + 8 * KA;
    const int colbase = h * HD + 2 * (lane & 3);
#pragma unroll
    for (int nt = 0; nt < 8; nt++) {
        const int col = colbase + nt * 8;
        *(uint32_t*)(outs + row0 + col) =
            cvt2h(acc_o[nt][0] * inv0, acc_o[nt][1] * inv0);
        *(uint32_t*)(outs + row1 + col) =
            cvt2h(acc_o[nt][2] * inv1, acc_o[nt][3] * inv1);
    }
}

// ---------------------------------------------------------------------------
extern "C" void kernel_launch(void* const* d_in, const int* in_sizes, int n_in,
                              void* d_out, int out_size)
{
    const float* x     = (const float*)d_in[0];
    const float* w_qkv = (const float*)d_in[1];
    const float* b_qkv = (const float*)d_in[2];
    const float* w_out = (const float*)d_in[3];
    const float* b_out = (const float*)d_in[4];
    float* out = (float*)d_out;

    __half *as, *wqkvs, *wouts, *qh, *kh, *vh;
    cudaGetSymbolAddress((void**)&as,    g_as);
    cudaGetSymbolAddress((void**)&wqkvs, g_wqkv_s);
    cudaGetSymbolAddress((void**)&wouts, g_wout_s);
    cudaGetSymbolAddress((void**)&qh, g_qh);
    cudaGetSymbolAddress((void**)&kh, g_kh);
    cudaGetSymbolAddress((void**)&vh, g_vh);

    cudaFuncSetAttribute(mma_gemm_kernel,
                         cudaFuncAttributeMaxDynamicSharedMemorySize, GEMM_SMEM);
    cudaFuncSetAttribute(attn_mma_kernel,
                         cudaFuncAttributeMaxDynamicSharedMemorySize, ATTN_SMEM);

    // 1) Convert weights (transpose, fp16)
    {
        dim3 grid(QKV_N / 32, HID / 32);
        convert_w_kernel<<<grid, 1024>>>(w_qkv, wqkvs, QKV_N);
    }
    {
        dim3 grid(HID / 32, HID / 32);
        convert_w_kernel<<<grid, 1024>>>(w_out, wouts, HID);
    }
    // 2) Convert x
    convert_act_kernel<<<(MROWS * 256 + 255) / 256, 256>>>(x, as, MROWS);
    // 3) QKV projection -> head-major fp16 Q/K/V (mode 1)
    {
        dim3 grid(QKV_N / BN, MROWS / BM);
        mma_gemm_kernel<<<grid, 128, GEMM_SMEM>>>(as, wqkvs, b_qkv, nullptr,
                                                  QKV_N, 1, qh, kh, vh);
    }
    // 4) HMMA flash attention -> fp16 g_as
    {
        dim3 grid(16, BATCH * NHEADS);
        attn_mma_kernel<<<grid, 256, ATTN_SMEM>>>(qh, kh, vh, as);
    }
    // 5) Output projection (mode 0)
    {
        dim3 grid(HID / BN, MROWS / BM);
        mma_gemm_kernel<<<grid, 128, GEMM_SMEM>>>(as, wouts, b_out, out,
                                                  HID, 0, nullptr, nullptr, nullptr);
    }
}

// round 16
// speedup vs baseline: 2.1213x; 1.0959x over previous
#include <cuda_runtime.h>
#include <cuda_fp16.h>
#include <cstdint>
#include <math.h>

// Problem constants
#define BATCH   2
#define SEQ     2048
#define HID     1024
#define NHEADS  16
#define HD      64
#define QKV_N   3072
#define MROWS   4096
#define KA      1024          // activations: single fp16 limb
#define KWB     1024          // weights: single fp16 limb

#define QSCALE  0.18033688f   // 0.125 * log2(e)

// ---------------- scratch (device globals; no allocations allowed) ----------
__device__ __half g_as[(size_t)MROWS * KA];            // activations fp16
__device__ __half g_wqkv_s[(size_t)QKV_N * KWB];       // W^T fp16
__device__ __half g_wout_s[(size_t)HID * KWB];
// Head-major fp16 Q/K/V (single limb): [b*16+h][s][64]
#define HM_ELEMS ((size_t)BATCH * NHEADS * SEQ * HD)
__device__ __half g_qh[HM_ELEMS];
__device__ __half g_kh[HM_ELEMS];
__device__ __half g_vh[HM_ELEMS];

// ---------------- PTX helpers (base ISA only) ----------------
__device__ __forceinline__ uint32_t smem_u32(const void* p) {
    uint32_t a;
    asm("{ .reg .u64 t; cvta.to.shared.u64 t, %1; cvt.u32.u64 %0, t; }" : "=r"(a) : "l"(p));
    return a;
}

__device__ __forceinline__ void cp_async16(uint32_t s, const void* g) {
    asm volatile("cp.async.cg.shared.global [%0], [%1], 16;" :: "r"(s), "l"(g) : "memory");
}
#define CP_COMMIT() asm volatile("cp.async.commit_group;" ::: "memory")
#define CP_WAIT1()  asm volatile("cp.async.wait_group 1;"  ::: "memory")

#define LDSM_X4(R0, R1, R2, R3, ADDR)                                          \
    asm volatile("ldmatrix.sync.aligned.m8n8.x4.shared.b16 {%0,%1,%2,%3}, [%4];" \
                 : "=r"(R0), "=r"(R1), "=r"(R2), "=r"(R3) : "r"(ADDR))

#define LDSM_X4T(R0, R1, R2, R3, ADDR)                                         \
    asm volatile("ldmatrix.sync.aligned.m8n8.x4.trans.shared.b16 {%0,%1,%2,%3}, [%4];" \
                 : "=r"(R0), "=r"(R1), "=r"(R2), "=r"(R3) : "r"(ADDR))

// fp16 inputs, f32 accumulate
#define MMAF32(D, A, B0, B1)                                                   \
    asm volatile("mma.sync.aligned.m16n8k16.row.col.f32.f16.f16.f32 "          \
                 "{%0,%1,%2,%3},{%4,%5,%6,%7},{%8,%9},{%0,%1,%2,%3};"          \
                 : "+f"((D)[0]), "+f"((D)[1]), "+f"((D)[2]), "+f"((D)[3])      \
                 : "r"((A)[0]), "r"((A)[1]), "r"((A)[2]), "r"((A)[3]),         \
                   "r"(B0), "r"(B1))

// exp2 via MUFU (1 issue slot; ~2 ulp).
__device__ __forceinline__ float fexp2(float x) {
    float y;
    asm("ex2.approx.f32 %0, %1;" : "=f"(y) : "f"(x));
    return y;
}

// pack two fp32 -> half2 in ONE instruction (lo in low half), rn rounding
__device__ __forceinline__ uint32_t cvt2h(float lo, float hi) {
    uint32_t r;
    asm("cvt.rn.f16x2.f32 %0, %1, %2;" : "=r"(r) : "f"(hi), "f"(lo));
    return r;
}

// ---------------------------------------------------------------------------
// Conversion: fp32 activations [R,1024] -> fp16 [R,1024]
// ---------------------------------------------------------------------------
__global__ __launch_bounds__(256) void convert_act_kernel(
    const float* __restrict__ in, __half* __restrict__ out, int R)
{
    int idx = blockIdx.x * 256 + threadIdx.x;     // over R*256 float4s
    if (idx >= R * 256) return;
    const float4 v = ((const float4*)in)[idx];
    uint2 h;
    h.x = cvt2h(v.x, v.y);
    h.y = cvt2h(v.z, v.w);
    ((uint2*)out)[idx] = h;
}

// ---------------------------------------------------------------------------
// Conversion + transpose: W fp32 [K=1024, N] -> fp16 [N,1024]
// ---------------------------------------------------------------------------
__global__ __launch_bounds__(1024) void convert_w_kernel(
    const float* __restrict__ w, __half* __restrict__ out, int N)
{
    __shared__ float tile[32][33];
    int tx = threadIdx.x & 31;
    int ty = threadIdx.x >> 5;
    int gn = blockIdx.x * 32;
    int gk = blockIdx.y * 32;
    tile[ty][tx] = w[(size_t)(gk + ty) * N + gn + tx];
    __syncthreads();
    out[(size_t)(gn + ty) * KWB + gk + tx] = __float2half(tile[tx][ty]);
}

// ---------------------------------------------------------------------------
// HMMA GEMM (unchanged from R15): C[4096,N] = A[4096,1024] @ B[N,1024]^T + bias.
// CTA tile 64x128xBK64, 128 threads (4 warps, 2x2), warp tile 32x64, 3 CTA/SM.
// mode 0: fp32 C out.  mode 1: QKV epilogue -> fp16 Q(scaled)/K/V head-major.
// ---------------------------------------------------------------------------
#define BM 64
#define BN 128
#define BK 64
#define NKITER (KA / BK)                   // 16
#define A_BYTES (BM * 128)                 // 8 KB
#define B_BYTES (BN * 128)                 // 16 KB
#define STAGE_BYTES (A_BYTES + B_BYTES)    // 24 KB
#define GEMM_SMEM (3 * STAGE_BYTES + 128)

__global__ __launch_bounds__(128, 3) void mma_gemm_kernel(
    const __half* __restrict__ As, const __half* __restrict__ Bs,
    const float* __restrict__ bias, float* __restrict__ C, int N, int mode,
    __half* __restrict__ qh, __half* __restrict__ kh, __half* __restrict__ vh)
{
    extern __shared__ char dsmem[];
    const uint32_t smem_base = (smem_u32(dsmem) + 127u) & ~127u;

    const int tid  = threadIdx.x;
    const int wid  = tid >> 5;
    const int lane = tid & 31;
    const int wm   = wid >> 1;     // 0..1 (32-row slab)
    const int wn   = wid & 1;      // 0..1 (64-col slab)

    const int block_row = blockIdx.y * BM;
    const int block_col = blockIdx.x * BN;

    const __half* Abase = As + (size_t)block_row * KA;
    const __half* Bbase = Bs + (size_t)block_col * KWB;

    auto load_stage = [&](int stage, int kc) {
        const uint32_t sA = smem_base + stage * STAGE_BYTES;
        const uint32_t sB = sA + A_BYTES;
#pragma unroll
        for (int i = 0; i < 4; i++) {       // A: 512 16B segs
            const int s   = i * 128 + tid;
            const int row = s >> 3;
            const int ch  = s & 7;
            const uint32_t sw = (uint32_t)(ch * 16) ^ (uint32_t)((row & 7) << 4);
            cp_async16(sA + row * 128 + sw, Abase + (size_t)row * KA + kc + ch * 8);
        }
#pragma unroll
        for (int i = 0; i < 8; i++) {       // B: 1024 16B segs
            const int s   = i * 128 + tid;
            const int row = s >> 3;
            const int ch  = s & 7;
            const uint32_t sw = (uint32_t)(ch * 16) ^ (uint32_t)((row & 7) << 4);
            cp_async16(sB + row * 128 + sw, Bbase + (size_t)row * KWB + kc + ch * 8);
        }
        CP_COMMIT();
    };

    float facc[2][8][4];
#pragma unroll
    for (int mt = 0; mt < 2; mt++)
#pragma unroll
        for (int nt = 0; nt < 8; nt++)
#pragma unroll
            for (int r = 0; r < 4; r++) facc[mt][nt][r] = 0.0f;

    load_stage(0, 0);
    load_stage(1, BK);

    const int lrow  = lane & 15;
    const int kseg  = (lane >> 4) * 16;
    const uint32_t arow_off = (uint32_t)(wm * 32 + lrow) * 128;
    const uint32_t brow_off = (uint32_t)(wn * 64 + lrow) * 128;
    const uint32_t aswz = (uint32_t)((lrow & 7) << 4);

    for (int it = 0; it < NKITER; it++) {
        CP_WAIT1();
        __syncthreads();
        if (it + 2 < NKITER) load_stage((it + 2) % 3, (it + 2) * BK);
        else                 CP_COMMIT();
        const uint32_t sA = smem_base + (it % 3) * STAGE_BYTES;
        const uint32_t sB = sA + A_BYTES;
#pragma unroll
        for (int kt = 0; kt < 4; kt++) {
            const uint32_t koff = ((uint32_t)(kt * 32 + kseg)) ^ aswz;
            uint32_t a[2][4], bb[4][4];
#pragma unroll
            for (int mt = 0; mt < 2; mt++)
                LDSM_X4(a[mt][0], a[mt][1], a[mt][2], a[mt][3],
                        sA + arow_off + (uint32_t)(mt * 2048) + koff);
#pragma unroll
            for (int pr = 0; pr < 4; pr++)
                LDSM_X4(bb[pr][0], bb[pr][1], bb[pr][2], bb[pr][3],
                        sB + brow_off + (uint32_t)(pr * 2048) + koff);
#pragma unroll
            for (int mt = 0; mt < 2; mt++)
#pragma unroll
                for (int nt = 0; nt < 8; nt++) {
                    const int pr = nt >> 1, sub = nt & 1;
                    MMAF32(facc[mt][nt], a[mt], bb[pr][sub], bb[pr][sub + 2]);
                }
        }
        __syncthreads();
    }

    const int rbase = block_row + wm * 32 + (lane >> 2);
    const int cbase = block_col + wn * 64 + (lane & 3) * 2;

#pragma unroll
    for (int mt = 0; mt < 2; mt++) {
#pragma unroll
        for (int nt = 0; nt < 8; nt++) {
            const int col = cbase + nt * 8;
            const float bx = bias[col];
            const float by = bias[col + 1];
            const float r00 = facc[mt][nt][0] + bx;
            const float r01 = facc[mt][nt][1] + by;
            const float r10 = facc[mt][nt][2] + bx;
            const float r11 = facc[mt][nt][3] + by;
            if (mode == 0) {
                const int r0 = rbase + mt * 16;
                float2 o0 = { r00, r01 };
                float2 o1 = { r10, r11 };
                *(float2*)(C + (size_t)r0 * N + col)       = o0;
                *(float2*)(C + (size_t)(r0 + 8) * N + col) = o1;
            } else {
                const int part = col >> 10;          // warp-uniform (64-col slab)
                const int hh   = (col >> 6) & 15;
                const int dd   = col & 63;
                __half* dst = part == 0 ? qh : (part == 1 ? kh : vh);
                const float sc = part == 0 ? QSCALE : 1.0f;
#pragma unroll
                for (int rr = 0; rr < 2; rr++) {
                    const int r = rbase + mt * 16 + rr * 8;
                    const float v0 = (rr ? r10 : r00) * sc;
                    const float v1 = (rr ? r11 : r01) * sc;
                    const size_t off =
                        (((size_t)((r >> 11) * 16 + hh)) * SEQ + (r & 2047)) * 64 + dd;
                    *(uint32_t*)(dst + off) = cvt2h(v0, v1);
                }
            }
        }
    }
}

// ---------------------------------------------------------------------------
// HMMA causal flash attention, PAIRED SCHEDULE: each CTA handles two
// q-blocks, qb = 15-bx then qb = bx, so every CTA does exactly 34 KV tiles.
// Grid 8 x 32 = 256 CTAs, 2 CTA/SM -> one balanced wave over 296 slots.
// Per-q-block math identical to R15 (bit-identical output).
// Single-limb fp16 Q/K/V, 2-stage cp.async pipeline, MUFU exp2 softmax.
// Output: fp16 [R,1024] rows of g_as.
// smem: QH 16K | 2 stages x {KH,VH 8K each} = 48KB (+pad)
// ---------------------------------------------------------------------------
#define KV_STAGE_BYTES 16384
#define ATTN_SMEM (16384 + 2 * KV_STAGE_BYTES + 128)

__global__ __launch_bounds__(256, 2) void attn_mma_kernel(
    const __half* __restrict__ qh_g,
    const __half* __restrict__ kh_g, const __half* __restrict__ vh_g,
    __half* __restrict__ outs)
{
    extern __shared__ char sm[];
    const uint32_t base = (smem_u32(sm) + 127u) & ~127u;
    const uint32_t sQH = base;
    const uint32_t kvbase = base + 16384;

    const int tid  = threadIdx.x;
    const int lane = tid & 31;
    const int wid  = tid >> 5;
    const int bx   = (int)blockIdx.x;          // 0..7
    const int bh   = blockIdx.y;
    const int b    = bh >> 4;
    const int h    = bh & 15;
    const size_t hrow = (size_t)bh * SEQ;

    auto load_kv = [&](int stage, int k0) {
        const uint32_t sb = kvbase + stage * KV_STAGE_BYTES;
#pragma unroll
        for (int i = 0; i < 2; i++) {
            const int s   = i * 256 + tid;
            const int row = s >> 3;
            const int ch  = s & 7;
            const uint32_t sw = (uint32_t)(ch * 16) ^ (uint32_t)((row & 7) << 4);
            const uint32_t so = row * 128 + sw;
            const size_t gofs = (hrow + k0 + row) * 64 + ch * 8;
            cp_async16(sb + so,        kh_g + gofs);
            cp_async16(sb + 8192 + so, vh_g + gofs);
        }
        CP_COMMIT();
    };

    // lane-derived constants (q-block independent)
    const int r0  = lane >> 2;
    const int a_r = wid * 16 + (lane & 15);
    const int a_c = (lane >> 4) * 16;
    const uint32_t a_row_off = (uint32_t)(a_r * 128);
    const uint32_t a_sw = (uint32_t)((a_r & 7) << 4);
    const int g      = lane >> 3;
    const int br_off = lane & 7;

    for (int half = 0; half < 2; half++) {
        const int qb = half == 0 ? 15 - bx : bx;   // heavy block first
        const int nk = (qb + 1) * 2;

        // ---- Q tile cp.async (joins the kv(0) group) ----
#pragma unroll
        for (int i = 0; i < 4; i++) {
            const int s   = i * 256 + tid;
            const int row = s >> 3;
            const int ch  = s & 7;
            const uint32_t sw = (uint32_t)(ch * 16) ^ (uint32_t)((row & 7) << 4);
            const size_t gofs = (hrow + qb * 128 + row) * 64 + ch * 8;
            cp_async16(sQH + row * 128 + sw, qh_g + gofs);
        }
        load_kv(0, 0);

        float acc_o[8][4];
#pragma unroll
        for (int nt = 0; nt < 8; nt++)
#pragma unroll
            for (int r = 0; r < 4; r++) acc_o[nt][r] = 0.0f;
        float m0 = -1e30f, m1 = -1e30f, l0 = 0.0f, l1 = 0.0f;

        const int qrow_w = qb * 128 + wid * 16;
        const int qg0    = qrow_w + r0;

        uint32_t qf[4][4];         // Q fragments (loaded at t==0)

        for (int t = 0; t < nk; t++) {
            const int k0 = t * 64;
            if (t + 1 < nk) load_kv((t + 1) & 1, (t + 1) * 64);
            else            CP_COMMIT();
            CP_WAIT1();            // stage t's group complete
            __syncthreads();

            if (t == 0) {          // hoisted Q fragment load
#pragma unroll
                for (int kc = 0; kc < 4; kc++) {
                    const uint32_t qoff = ((uint32_t)(kc * 32 + a_c)) ^ a_sw;
                    LDSM_X4(qf[kc][0], qf[kc][1], qf[kc][2], qf[kc][3],
                            sQH + a_row_off + qoff);
                }
            }

            const uint32_t st  = kvbase + (t & 1) * KV_STAGE_BYTES;
            const uint32_t sKH = st;
            const uint32_t sVH = st + 8192;

            // ---- S = Q K^T (f32 acc) ----
            float s[8][4];
#pragma unroll
            for (int nt = 0; nt < 8; nt++)
#pragma unroll
                for (int r = 0; r < 4; r++) s[nt][r] = 0.0f;

#pragma unroll
            for (int kc = 0; kc < 4; kc++) {
#pragma unroll
                for (int np = 0; np < 4; np++) {
                    const int brow = np * 16 + ((g & 2) << 2) + br_off;
                    const uint32_t boff = ((uint32_t)(kc * 32 + ((g & 1) << 4)))
                                        ^ (uint32_t)((brow & 7) << 4);
                    const uint32_t rb = (uint32_t)(brow * 128) + boff;
                    uint32_t kh0, kh1, kh2, kh3;
                    LDSM_X4(kh0, kh1, kh2, kh3, sKH + rb);
                    MMAF32(s[2 * np],     qf[kc], kh0, kh1);
                    MMAF32(s[2 * np + 1], qf[kc], kh2, kh3);
                }
            }

            // ---- causal mask ----
            if (k0 + 63 > qrow_w) {
#pragma unroll
                for (int nt = 0; nt < 8; nt++) {
                    const int kg0 = k0 + nt * 8 + 2 * (lane & 3);
                    if (kg0     > qg0)     s[nt][0] = -1e30f;
                    if (kg0 + 1 > qg0)     s[nt][1] = -1e30f;
                    if (kg0     > qg0 + 8) s[nt][2] = -1e30f;
                    if (kg0 + 1 > qg0 + 8) s[nt][3] = -1e30f;
                }
            }

            // ---- online softmax (base-2, MUFU exp2) ----
            float rx0 = -1e30f, rx1 = -1e30f;
#pragma unroll
            for (int nt = 0; nt < 8; nt++) {
                rx0 = fmaxf(rx0, fmaxf(s[nt][0], s[nt][1]));
                rx1 = fmaxf(rx1, fmaxf(s[nt][2], s[nt][3]));
            }
            rx0 = fmaxf(rx0, __shfl_xor_sync(0xffffffffu, rx0, 1));
            rx0 = fmaxf(rx0, __shfl_xor_sync(0xffffffffu, rx0, 2));
            rx1 = fmaxf(rx1, __shfl_xor_sync(0xffffffffu, rx1, 1));
            rx1 = fmaxf(rx1, __shfl_xor_sync(0xffffffffu, rx1, 2));
            const float mn0 = fmaxf(m0, rx0);
            const float mn1 = fmaxf(m1, rx1);
            const float sc0 = fexp2(m0 - mn0);
            const float sc1 = fexp2(m1 - mn1);
            m0 = mn0; m1 = mn1;
            l0 *= sc0; l1 *= sc1;
#pragma unroll
            for (int nt = 0; nt < 8; nt++) {
                acc_o[nt][0] *= sc0; acc_o[nt][1] *= sc0;
                acc_o[nt][2] *= sc1; acc_o[nt][3] *= sc1;
            }

            uint32_t ph[4][4];
#pragma unroll
            for (int nt = 0; nt < 8; nt++) {
                const float p0 = fexp2(s[nt][0] - m0);
                const float p1 = fexp2(s[nt][1] - m0);
                const float p2 = fexp2(s[nt][2] - m1);
                const float p3 = fexp2(s[nt][3] - m1);
                l0 += p0 + p1;
                l1 += p2 + p3;
                const int kc = nt >> 1;
                const int rr = (nt & 1) * 2;
                ph[kc][rr]     = cvt2h(p0, p1);
                ph[kc][rr + 1] = cvt2h(p2, p3);
            }

            // ---- O += P V (f32 acc, ldmatrix.trans for V) ----
#pragma unroll
            for (int kc = 0; kc < 4; kc++) {
#pragma unroll
                for (int np = 0; np < 4; np++) {
                    const int vrow = kc * 16 + ((g & 1) << 3) + br_off;
                    const uint32_t voff = ((uint32_t)(np * 32 + ((g & 2) << 3)))
                                        ^ (uint32_t)((vrow & 7) << 4);
                    const uint32_t rv = (uint32_t)(vrow * 128) + voff;
                    uint32_t vh0, vh1, vh2, vh3;
                    LDSM_X4T(vh0, vh1, vh2, vh3, sVH + rv);
                    MMAF32(acc_o[2 * np],     ph[kc], vh0, vh1);
                    MMAF32(acc_o[2 * np + 1], ph[kc], vh2, vh3);
                }
            }
            __syncthreads();   // buffer (t&1) free; also frees sQH at t=nk-1
        }

        // ---- normalize, write fp16 [R,1024] rows of g_as ----
        l0 += __shfl_xor_sync(0xffffffffu, l0, 1);
        l0 += __shfl_xor_sync(0xffffffffu, l0, 2);
        l1 += __shfl_xor_sync(0xffffffffu, l1, 1);
        l1 += __shfl_xor_sync(0xffffffffu, l1, 2);
        const float inv0 = 1.0f / l0;
        const float inv1 = 1.0f / l1;

        const size_t row0 = (size_t)(b * SEQ + qg0) * KA;
        const size_t row1 = row0 + 8 * KA;
        const int colbase = h * HD + 2 * (lane & 3);
#pragma unroll
        for (int nt = 0; nt < 8; nt++) {
            const int col = colbase + nt * 8;
            *(uint32_t*)(outs + row0 + col) =
                cvt2h(acc_o[nt][0] * inv0, acc_o[nt][1] * inv0);
            *(uint32_t*)(outs + row1 + col) =
                cvt2h(acc_o[nt][2] * inv1, acc_o[nt][3] * inv1);
        }
    }
}

// ---------------------------------------------------------------------------
extern "C" void kernel_launch(void* const* d_in, const int* in_sizes, int n_in,
                              void* d_out, int out_size)
{
    const float* x     = (const float*)d_in[0];
    const float* w_qkv = (const float*)d_in[1];
    const float* b_qkv = (const float*)d_in[2];
    const float* w_out = (const float*)d_in[3];
    const float* b_out = (const float*)d_in[4];
    float* out = (float*)d_out;

    __half *as, *wqkvs, *wouts, *qh, *kh, *vh;
    cudaGetSymbolAddress((void**)&as,    g_as);
    cudaGetSymbolAddress((void**)&wqkvs, g_wqkv_s);
    cudaGetSymbolAddress((void**)&wouts, g_wout_s);
    cudaGetSymbolAddress((void**)&qh, g_qh);
    cudaGetSymbolAddress((void**)&kh, g_kh);
    cudaGetSymbolAddress((void**)&vh, g_vh);

    cudaFuncSetAttribute(mma_gemm_kernel,
                         cudaFuncAttributeMaxDynamicSharedMemorySize, GEMM_SMEM);
    cudaFuncSetAttribute(attn_mma_kernel,
                         cudaFuncAttributeMaxDynamicSharedMemorySize, ATTN_SMEM);

    // 1) Convert weights (transpose, fp16)
    {
        dim3 grid(QKV_N / 32, HID / 32);
        convert_w_kernel<<<grid, 1024>>>(w_qkv, wqkvs, QKV_N);
    }
    {
        dim3 grid(HID / 32, HID / 32);
        convert_w_kernel<<<grid, 1024>>>(w_out, wouts, HID);
    }
    // 2) Convert x
    convert_act_kernel<<<(MROWS * 256 + 255) / 256, 256>>>(x, as, MROWS);
    // 3) QKV projection -> head-major fp16 Q/K/V (mode 1)
    {
        dim3 grid(QKV_N / BN, MROWS / BM);
        mma_gemm_kernel<<<grid, 128, GEMM_SMEM>>>(as, wqkvs, b_qkv, nullptr,
                                                  QKV_N, 1, qh, kh, vh);
    }
    // 4) HMMA flash attention (paired balanced schedule) -> fp16 g_as
    {
        dim3 grid(8, BATCH * NHEADS);
        attn_mma_kernel<<<grid, 256, ATTN_SMEM>>>(qh, kh, vh, as);
    }
    // 5) Output projection (mode 0)
    {
        dim3 grid(HID / BN, MROWS / BM);
        mma_gemm_kernel<<<grid, 128, GEMM_SMEM>>>(as, wouts, b_out, out,
                                                  HID, 0, nullptr, nullptr, nullptr);
    }
}